// round 6
// baseline (speedup 1.0000x reference)
#include <cuda_runtime.h>
#include <cuda_bf16.h>
#include <cstdint>

// ---------------- problem constants ----------------
#define N_NODES  50000
#define E_MAX    450000
#define NFEAT    512
#define NHID     64
#define NHEADS   8
#define NOUT     128
#define X2DIM    512

// ---------------- device scratch ----------------
__device__ float g_h_all[(size_t)N_NODES * X2DIM];
__device__ float g_x2  [(size_t)N_NODES * X2DIM];   // layer-2 input, fp32
__device__ float g_s1  [N_NODES * NHEADS];
__device__ float g_s2  [N_NODES * NHEADS];
__device__ float g_hml [(size_t)N_NODES * 256];     // [:,0:128]=h_mu, [:,128:256]=h_lv
__device__ float g_smu1[N_NODES], g_smu2[N_NODES], g_slv1[N_NODES], g_slv2[N_NODES];
__device__ int   g_rowptr[N_NODES + 1];
__device__ int   g_col [E_MAX];
__device__ int   g_cnt [N_NODES];
__device__ int   g_cursor[N_NODES];

// bf16 hi/lo split weights
__device__ __nv_bfloat16 g_bt1h[512 * 512], g_bt1l[512 * 512];   // Ws^T   [512,512]
__device__ __nv_bfloat16 g_bt2h[256 * 512], g_bt2l[256 * 512];   // [muW;lvW]^T [256,512]

// ---------------- PTX helpers (target-generic, sm_80+) ----------------
__device__ __forceinline__ unsigned smem_u32(const void* p) {
    unsigned r;
    asm("{ .reg .u64 t; cvta.to.shared.u64 t, %1; cvt.u32.u64 %0, t; }"
        : "=r"(r) : "l"(p));
    return r;
}
__device__ __forceinline__ void cp16(unsigned dst, const void* src, int srcsz) {
    asm volatile("cp.async.cg.shared.global [%0], [%1], 16, %2;"
                 :: "r"(dst), "l"(src), "r"(srcsz) : "memory");
}
__device__ __forceinline__ void cp_commit() {
    asm volatile("cp.async.commit_group;" ::: "memory");
}
__device__ __forceinline__ void ldsm4(unsigned& r0, unsigned& r1, unsigned& r2,
                                      unsigned& r3, unsigned a) {
    asm volatile("ldmatrix.sync.aligned.m8n8.x4.shared.b16 {%0,%1,%2,%3}, [%4];"
                 : "=r"(r0), "=r"(r1), "=r"(r2), "=r"(r3) : "r"(a));
}
__device__ __forceinline__ void mma16816(float* d, const unsigned* a, const unsigned* b) {
    asm volatile(
        "mma.sync.aligned.m16n8k16.row.col.f32.bf16.bf16.f32 "
        "{%0,%1,%2,%3}, {%4,%5,%6,%7}, {%8,%9}, {%0,%1,%2,%3};"
        : "+f"(d[0]), "+f"(d[1]), "+f"(d[2]), "+f"(d[3])
        : "r"(a[0]), "r"(a[1]), "r"(a[2]), "r"(a[3]), "r"(b[0]), "r"(b[1]));
}
// swizzled byte offset inside a tile whose rows are 64 bf16 = 128B
__device__ __forceinline__ unsigned aoff(int r, int k) {
    return (unsigned)((r << 7) + (((((k >> 3) ^ r) & 7)) << 4) + ((k & 7) << 1));
}

// ---------------- CSR construction ----------------
__global__ void zero_kernel(int n) {
    int i = blockIdx.x * blockDim.x + threadIdx.x;
    if (i < n) { g_cnt[i] = 0; g_cursor[i] = 0; }
}
__global__ void hist_kernel(const int* __restrict__ ei, int E) {
    int e = blockIdx.x * blockDim.x + threadIdx.x;
    if (e < E) atomicAdd(&g_cnt[ei[e]], 1);
}
__global__ void scan_kernel(int n) {
    __shared__ int sh[1024];
    __shared__ int carry;
    if (threadIdx.x == 0) carry = 0;
    __syncthreads();
    for (int base = 0; base < n; base += 1024) {
        int i = base + threadIdx.x;
        int v = (i < n) ? g_cnt[i] : 0;
        sh[threadIdx.x] = v;
        __syncthreads();
        for (int off = 1; off < 1024; off <<= 1) {
            int t = (threadIdx.x >= off) ? sh[threadIdx.x - off] : 0;
            __syncthreads();
            sh[threadIdx.x] += t;
            __syncthreads();
        }
        if (i < n) g_rowptr[i] = carry + sh[threadIdx.x] - v;
        __syncthreads();
        if (threadIdx.x == 0) carry += sh[1023];
        __syncthreads();
    }
    if (threadIdx.x == 0) g_rowptr[n] = carry;
}
__global__ void fill_kernel(const int* __restrict__ ei, int E) {
    int e = blockIdx.x * blockDim.x + threadIdx.x;
    if (e < E) {
        int s = ei[e];
        int d = ei[E + e];
        int p = atomicAdd(&g_cursor[s], 1);
        g_col[g_rowptr[s] + p] = d;
    }
}

// ---------------- weight conversion (bf16 hi/lo) ----------------
__global__ void convert_w_kernel(const float* __restrict__ Ws,
                                 const float* __restrict__ muW,
                                 const float* __restrict__ lvW) {
    int i = blockIdx.x * blockDim.x + threadIdx.x;
    float v;
    __nv_bfloat16 *ph, *pl;
    if (i < 512 * 512) {
        int row = i >> 9, k = i & 511;            // row = h*64 + n
        int h = row >> 6, n = row & 63;
        v = Ws[((size_t)h * 512 + k) * 64 + n];
        ph = g_bt1h + i; pl = g_bt1l + i;
    } else if (i < 512 * 512 + 256 * 512) {
        int j = i - 512 * 512;
        int n = j >> 9, k = j & 511;
        v = (n < 128) ? muW[(size_t)k * 128 + n]
                      : lvW[(size_t)k * 128 + (n - 128)];
        ph = g_bt2h + j; pl = g_bt2l + j;
    } else return;
    __nv_bfloat16 hv = __float2bfloat16_rn(v);
    *ph = hv;
    *pl = __float2bfloat16_rn(v - __bfloat162float(hv));
}

// ---------------- HMMA bf16x3 GEMM, fused fp32->bf16 split on A ------------
// C[m0:+128, nb:+128] = A[M,512](fp32) * Bt[nb:+128, 512]^T
// A loaded via LDG float4 -> register prefetch -> convert + STS (hi/lo).
// B (pre-split bf16) via cp.async 2-stage.
// Stage: Ah 16K | Al 16K | Bh 16K | Bl 16K = 64KB, 2 stages = 128KB.
#define KC 64
#define STAGE 65536

__device__ __forceinline__ void ldgA(float4* areg, const float* __restrict__ A,
                                     int m0, int k0, int M, int tid) {
#pragma unroll
    for (int it = 0; it < 4; it++) {
        int idx = it * 512 + tid;
        int r = idx >> 4, g = idx & 15;
        int row = m0 + r;
        areg[it] = (row < M)
            ? *(const float4*)(A + (size_t)row * 512 + k0 + g * 4)
            : make_float4(0.f, 0.f, 0.f, 0.f);
    }
}

__device__ __forceinline__ void stsA(unsigned st, const float4* areg, int tid) {
#pragma unroll
    for (int it = 0; it < 4; it++) {
        int idx = it * 512 + tid;
        int r = idx >> 4, g = idx & 15;
        int k = g * 4;
        unsigned off = (unsigned)((r << 7) + ((((k >> 3) ^ r) & 7) << 4)
                                 + ((k & 7) << 1));
        float4 v = areg[it];
        __nv_bfloat16 h0 = __float2bfloat16_rn(v.x);
        __nv_bfloat16 h1 = __float2bfloat16_rn(v.y);
        __nv_bfloat16 h2 = __float2bfloat16_rn(v.z);
        __nv_bfloat16 h3 = __float2bfloat16_rn(v.w);
        __nv_bfloat162 hA(h0, h1), hB(h2, h3);
        __nv_bfloat162 lA(__float2bfloat16_rn(v.x - __bfloat162float(h0)),
                          __float2bfloat16_rn(v.y - __bfloat162float(h1)));
        __nv_bfloat162 lB(__float2bfloat16_rn(v.z - __bfloat162float(h2)),
                          __float2bfloat16_rn(v.w - __bfloat162float(h3)));
        uint2 hi, lo;
        hi.x = *(unsigned*)&hA; hi.y = *(unsigned*)&hB;
        lo.x = *(unsigned*)&lA; lo.y = *(unsigned*)&lB;
        asm volatile("st.shared.v2.u32 [%0], {%1,%2};"
                     :: "r"(st + off), "r"(hi.x), "r"(hi.y) : "memory");
        asm volatile("st.shared.v2.u32 [%0], {%1,%2};"
                     :: "r"(st + 16384 + off), "r"(lo.x), "r"(lo.y) : "memory");
    }
}

__device__ __forceinline__ void ldB(unsigned st, const __nv_bfloat16* Bh,
                                    const __nv_bfloat16* Bl, int k0, int tid) {
#pragma unroll
    for (int it = 0; it < 2; it++) {
        int idx = it * 512 + tid;
        int r = idx >> 3, c = idx & 7;
        unsigned d = st + 32768u + (unsigned)((r << 7) + (((c ^ (r & 7)) & 7) << 4));
        size_t go = (size_t)r * 512 + k0 + c * 8;
        cp16(d,         Bh + go, 16);
        cp16(d + 16384, Bl + go, 16);
    }
}

__global__ __launch_bounds__(512) void gemm_tc(
    const float* __restrict__ A,
    const __nv_bfloat16* __restrict__ Bhg, const __nv_bfloat16* __restrict__ Blg,
    float* __restrict__ C, int M, int ldc)
{
    extern __shared__ char smem[];
    const unsigned sbase = smem_u32(smem);
    const int tid = threadIdx.x, lane = tid & 31, wid = tid >> 5;
    const int m0 = blockIdx.y * 128;        // n-tile fastest -> A L2 reuse
    const int nb = blockIdx.x * 128;
    C += nb;
    const __nv_bfloat16* Bh = Bhg + (size_t)nb * 512;
    const __nv_bfloat16* Bl = Blg + (size_t)nb * 512;
    const int wm = (wid & 3) * 32, wn = (wid >> 2) * 32;

    float acc[2][4][4];
#pragma unroll
    for (int i = 0; i < 2; i++)
#pragma unroll
        for (int j = 0; j < 4; j++)
#pragma unroll
            for (int q = 0; q < 4; q++) acc[i][j][q] = 0.f;

    float4 areg[4];
    ldgA(areg, A, m0, 0, M, tid);
    ldB(sbase, Bh, Bl, 0, tid);
    cp_commit();
    ldB(sbase + STAGE, Bh, Bl, KC, tid);
    cp_commit();

    for (int kc = 0; kc < 8; kc++) {
        const unsigned st = sbase + (kc & 1) * STAGE;
        stsA(st, areg, tid);                         // convert+store chunk kc
        if (kc < 7) {
            ldgA(areg, A, m0, (kc + 1) * KC, M, tid); // prefetch next A
            asm volatile("cp.async.wait_group 1;" ::: "memory");
        } else {
            asm volatile("cp.async.wait_group 0;" ::: "memory");
        }
        __syncthreads();
#pragma unroll
        for (int kk = 0; kk < 4; kk++) {
            const int k = kk * 16;
            int ar = lane & 15;
            int ac = k + ((lane >> 4) << 3);
            unsigned ah[2][4], al[2][4];
            ldsm4(ah[0][0], ah[0][1], ah[0][2], ah[0][3], st + aoff(wm + ar, ac));
            ldsm4(ah[1][0], ah[1][1], ah[1][2], ah[1][3], st + aoff(wm + 16 + ar, ac));
            ldsm4(al[0][0], al[0][1], al[0][2], al[0][3], st + 16384 + aoff(wm + ar, ac));
            ldsm4(al[1][0], al[1][1], al[1][2], al[1][3], st + 16384 + aoff(wm + 16 + ar, ac));
            int br = (lane & 7) + ((lane >> 4) << 3);
            int bc = k + (((lane >> 3) & 1) << 3);
            unsigned bh[4][2], bl[4][2];
            ldsm4(bh[0][0], bh[0][1], bh[1][0], bh[1][1],
                  st + 32768 + aoff(wn + br, bc));
            ldsm4(bh[2][0], bh[2][1], bh[3][0], bh[3][1],
                  st + 32768 + aoff(wn + 16 + br, bc));
            ldsm4(bl[0][0], bl[0][1], bl[1][0], bl[1][1],
                  st + 49152 + aoff(wn + br, bc));
            ldsm4(bl[2][0], bl[2][1], bl[3][0], bl[3][1],
                  st + 49152 + aoff(wn + 16 + br, bc));
#pragma unroll
            for (int mt = 0; mt < 2; mt++)
#pragma unroll
                for (int nt = 0; nt < 4; nt++) {
                    mma16816(acc[mt][nt], ah[mt], bh[nt]);
                    mma16816(acc[mt][nt], ah[mt], bl[nt]);
                    mma16816(acc[mt][nt], al[mt], bh[nt]);
                }
        }
        __syncthreads();
        if (kc + 2 < 8) {
            ldB(st, Bh, Bl, (kc + 2) * KC, tid);     // refill just-freed stage
            cp_commit();
        }
    }

#pragma unroll
    for (int mt = 0; mt < 2; mt++) {
        int r0 = m0 + wm + mt * 16 + (lane >> 2);
#pragma unroll
        for (int nt = 0; nt < 4; nt++) {
            int c0 = wn + nt * 8 + (lane & 3) * 2;
            if (r0 < M)
                *(float2*)&C[(size_t)r0 * ldc + c0] =
                    make_float2(acc[mt][nt][0], acc[mt][nt][1]);
            if (r0 + 8 < M)
                *(float2*)&C[(size_t)(r0 + 8) * ldc + c0] =
                    make_float2(acc[mt][nt][2], acc[mt][nt][3]);
        }
    }
}

// ---------------- layer-1 attention scalars ----------------
__global__ __launch_bounds__(256) void scalars1_kernel(const float* __restrict__ As) {
    int n = blockIdx.x;
    int w = threadIdx.x >> 5, lane = threadIdx.x & 31;
    const float* hr = g_h_all + (size_t)n * X2DIM + w * NHID;
    float v0 = hr[lane], v1 = hr[lane + 32];
    const float* a = As + w * 2 * NHID;
    float d1 = v0 * a[lane]      + v1 * a[lane + 32];
    float d2 = v0 * a[64 + lane] + v1 * a[96 + lane];
#pragma unroll
    for (int o = 16; o; o >>= 1) {
        d1 += __shfl_down_sync(0xffffffffu, d1, o);
        d2 += __shfl_down_sync(0xffffffffu, d2, o);
    }
    if (lane == 0) { g_s1[n * 8 + w] = d1; g_s2[n * 8 + w] = d2; }
}

// ---------------- layer-1 edge aggregation (float4) + elu -> fp32 x2 -------
__global__ __launch_bounds__(128) void agg1_kernel() {
    int n = blockIdx.x;
    int t = threadIdx.x;
    __shared__ float sh_s1[8];
    __shared__ float sh_den[8];
    __shared__ float sh_e[16 * 8];
    __shared__ int   sh_dst[16];
    if (t < 8) { sh_s1[t] = g_s1[n * 8 + t]; sh_den[t] = 0.f; }
    __syncthreads();
    int beg = g_rowptr[n], end = g_rowptr[n + 1];
    float4 acc = make_float4(0.f, 0.f, 0.f, 0.f);
    const int h = t >> 4;                  // cols 4t..4t+3 all in head t>>4
    for (int eb = beg; eb < end; eb += 16) {
        int cnt = min(16, end - eb);
        if (t < cnt) sh_dst[t] = g_col[eb + t];
        __syncthreads();
        if (t < cnt * 8) {
            int le = t >> 3, hh = t & 7;
            int d = sh_dst[le];
            float logit = sh_s1[hh] + g_s2[d * 8 + hh];
            float lr = logit > 0.f ? logit : 0.2f * logit;
            float e = __expf(-lr);
            sh_e[t] = e;
            atomicAdd(&sh_den[hh], e);
        }
        __syncthreads();
        for (int le = 0; le < cnt; le++) {
            int d = sh_dst[le];
            float w = sh_e[le * 8 + h];
            float4 v = *(const float4*)(g_h_all + (size_t)d * X2DIM + t * 4);
            acc.x += w * v.x; acc.y += w * v.y;
            acc.z += w * v.z; acc.w += w * v.w;
        }
        __syncthreads();
    }
    float inv = 1.f / sh_den[h];
    float v0 = acc.x * inv, v1 = acc.y * inv, v2 = acc.z * inv, v3 = acc.w * inv;
    v0 = v0 > 0.f ? v0 : expm1f(v0);
    v1 = v1 > 0.f ? v1 : expm1f(v1);
    v2 = v2 > 0.f ? v2 : expm1f(v2);
    v3 = v3 > 0.f ? v3 : expm1f(v3);
    *(float4*)(g_x2 + (size_t)n * X2DIM + t * 4) = make_float4(v0, v1, v2, v3);
}

// ---------------- layer-2 attention scalars ----------------
__global__ __launch_bounds__(128) void scalars2_kernel(
    const float* __restrict__ mua, const float* __restrict__ lva)
{
    int n = blockIdx.x, t = threadIdx.x;
    float hmu = g_hml[(size_t)n * 256 + t];
    float hlv = g_hml[(size_t)n * 256 + 128 + t];
    float p0 = hmu * mua[t];
    float p1 = hmu * mua[128 + t];
    float p2 = hlv * lva[t];
    float p3 = hlv * lva[128 + t];
#pragma unroll
    for (int o = 16; o; o >>= 1) {
        p0 += __shfl_down_sync(0xffffffffu, p0, o);
        p1 += __shfl_down_sync(0xffffffffu, p1, o);
        p2 += __shfl_down_sync(0xffffffffu, p2, o);
        p3 += __shfl_down_sync(0xffffffffu, p3, o);
    }
    __shared__ float red[4][4];
    int w = t >> 5, lane = t & 31;
    if (lane == 0) { red[w][0] = p0; red[w][1] = p1; red[w][2] = p2; red[w][3] = p3; }
    __syncthreads();
    if (t == 0) {
        g_smu1[n] = red[0][0] + red[1][0] + red[2][0] + red[3][0];
        g_smu2[n] = red[0][1] + red[1][1] + red[2][1] + red[3][1];
        g_slv1[n] = red[0][2] + red[1][2] + red[2][2] + red[3][2];
        g_slv2[n] = red[0][3] + red[1][3] + red[2][3] + red[3][3];
    }
}

// ---------------- layer-2 edge aggregation + reparameterize ----------------
__global__ __launch_bounds__(128) void agg2_kernel(
    const float* __restrict__ eps, float* __restrict__ out, int n_total)
{
    int n = blockIdx.x, t = threadIdx.x;
    __shared__ float sh_w[2][32];
    __shared__ int   sh_dst[32];
    __shared__ float sden[2];
    __shared__ float sval[256];
    if (t < 2) sden[t] = 0.f;
    float base_mu = g_smu1[n];
    float base_lv = g_slv1[n];
    __syncthreads();
    int beg = g_rowptr[n], end = g_rowptr[n + 1];
    const int sel = t >> 6;
    float2 acc = make_float2(0.f, 0.f);
    for (int eb = beg; eb < end; eb += 32) {
        int cnt = min(32, end - eb);
        if (t < cnt) {
            int d = g_col[eb + t];
            sh_dst[t] = d;
            float lmu = base_mu + g_smu2[d];
            float llv = base_lv + g_slv2[d];
            lmu = lmu > 0.f ? lmu : 0.2f * lmu;
            llv = llv > 0.f ? llv : 0.2f * llv;
            float emu = __expf(-lmu);
            float elv = __expf(-llv);
            sh_w[0][t] = emu; sh_w[1][t] = elv;
            atomicAdd(&sden[0], emu);
            atomicAdd(&sden[1], elv);
        }
        __syncthreads();
        for (int le = 0; le < cnt; le++) {
            int d = sh_dst[le];
            float w = sh_w[sel][le];
            float2 v = *(const float2*)(g_hml + (size_t)d * 256 + 2 * t);
            acc.x += w * v.x;
            acc.y += w * v.y;
        }
        __syncthreads();
    }
    float inv = 1.f / sden[sel];
    sval[2 * t]     = acc.x * inv;
    sval[2 * t + 1] = acc.y * inv;
    __syncthreads();
    float mu = sval[t];
    float lv = sval[128 + t];
    float z  = eps[(size_t)n * NOUT + t] * expf(lv) + mu;
    size_t NO = (size_t)n_total * NOUT;
    out[(size_t)n * NOUT + t]          = z;
    out[NO + (size_t)n * NOUT + t]     = mu;
    out[2 * NO + (size_t)n * NOUT + t] = lv;
}

// ---------------- host orchestration ----------------
extern "C" void kernel_launch(void* const* d_in, const int* in_sizes, int n_in,
                              void* d_out, int out_size)
{
    const float* x   = (const float*)d_in[0];
    const float* Ws  = (const float*)d_in[1];
    const float* As  = (const float*)d_in[2];
    const float* muW = (const float*)d_in[3];
    const float* mua = (const float*)d_in[4];
    const float* lvW = (const float*)d_in[5];
    const float* lva = (const float*)d_in[6];
    const float* eps = (const float*)d_in[7];
    const int*   ei  = (const int*)d_in[8];
    int E = in_sizes[8] / 2;
    int N = in_sizes[0] / NFEAT;
    float* out = (float*)d_out;

    float *p_hall, *p_x2, *p_hml;
    __nv_bfloat16 *p_bt1h, *p_bt1l, *p_bt2h, *p_bt2l;
    cudaGetSymbolAddress((void**)&p_hall, g_h_all);
    cudaGetSymbolAddress((void**)&p_x2,   g_x2);
    cudaGetSymbolAddress((void**)&p_hml,  g_hml);
    cudaGetSymbolAddress((void**)&p_bt1h, g_bt1h);
    cudaGetSymbolAddress((void**)&p_bt1l, g_bt1l);
    cudaGetSymbolAddress((void**)&p_bt2h, g_bt2h);
    cudaGetSymbolAddress((void**)&p_bt2l, g_bt2l);

    cudaFuncSetAttribute(gemm_tc, cudaFuncAttributeMaxDynamicSharedMemorySize,
                         2 * STAGE);

    int mtiles = (N + 127) / 128;

    // Launch order places gemm_tc (layer-1) at the ncu-profiled slot (#3).
    convert_w_kernel<<<(512 * 512 + 256 * 512 + 255) / 256, 256>>>(Ws, muW, lvW); // 0
    zero_kernel<<<(N + 255) / 256, 256>>>(N);                                     // 1
    hist_kernel<<<(E + 255) / 256, 256>>>(ei, E);                                 // 2
    gemm_tc<<<dim3(4, mtiles), 512, 2 * STAGE>>>(x, p_bt1h, p_bt1l,               // 3
                                                 p_hall, N, X2DIM);
    scan_kernel<<<1, 1024>>>(N);                                                  // 4
    fill_kernel<<<(E + 255) / 256, 256>>>(ei, E);                                 // 5
    scalars1_kernel<<<N, 256>>>(As);                                              // 6
    agg1_kernel<<<N, 128>>>();                                                    // 7
    gemm_tc<<<dim3(2, mtiles), 512, 2 * STAGE>>>(p_x2, p_bt2h, p_bt2l,            // 8
                                                 p_hml, N, 256);
    scalars2_kernel<<<N, 128>>>(mua, lva);                                        // 9
    agg2_kernel<<<N, 128>>>(eps, out, N);                                         // 10
}

// round 7
// speedup vs baseline: 1.2640x; 1.2640x over previous
#include <cuda_runtime.h>
#include <cuda_fp16.h>
#include <cstdint>

// ---------------- problem constants ----------------
#define N_NODES  50000
#define E_MAX    450000
#define NFEAT    512
#define NHID     64
#define NHEADS   8
#define NOUT     128
#define X2DIM    512

// ---------------- device scratch ----------------
__device__ float g_h_all[(size_t)N_NODES * X2DIM];
__device__ float g_s1  [N_NODES * NHEADS];
__device__ float g_s2  [N_NODES * NHEADS];
__device__ float g_hml [(size_t)N_NODES * 256];     // [:,0:128]=h_mu, [:,128:256]=h_lv
__device__ float g_smu1[N_NODES], g_smu2[N_NODES], g_slv1[N_NODES], g_slv2[N_NODES];
__device__ int   g_rowptr[N_NODES + 1];
__device__ int   g_col [E_MAX];
__device__ int   g_cnt [N_NODES];
__device__ int   g_cursor[N_NODES];

// fp16 2-limb activations, fp16 1-limb weights
__device__ __half g_xh [(size_t)N_NODES * NFEAT];
__device__ __half g_xl [(size_t)N_NODES * NFEAT];
__device__ __half g_x2h[(size_t)N_NODES * X2DIM];
__device__ __half g_x2l[(size_t)N_NODES * X2DIM];
__device__ __half g_bt1[512 * 512];                 // Ws^T        [512,512]
__device__ __half g_bt2[256 * 512];                 // [muW;lvW]^T [256,512]

// ---------------- PTX helpers (target-generic, sm_80+) ----------------
__device__ __forceinline__ unsigned smem_u32(const void* p) {
    unsigned r;
    asm("{ .reg .u64 t; cvta.to.shared.u64 t, %1; cvt.u32.u64 %0, t; }"
        : "=r"(r) : "l"(p));
    return r;
}
__device__ __forceinline__ void cp16(unsigned dst, const void* src, int srcsz) {
    asm volatile("cp.async.cg.shared.global [%0], [%1], 16, %2;"
                 :: "r"(dst), "l"(src), "r"(srcsz) : "memory");
}
__device__ __forceinline__ void cp_commit() {
    asm volatile("cp.async.commit_group;" ::: "memory");
}
__device__ __forceinline__ void ldsm4(unsigned& r0, unsigned& r1, unsigned& r2,
                                      unsigned& r3, unsigned a) {
    asm volatile("ldmatrix.sync.aligned.m8n8.x4.shared.b16 {%0,%1,%2,%3}, [%4];"
                 : "=r"(r0), "=r"(r1), "=r"(r2), "=r"(r3) : "r"(a));
}
__device__ __forceinline__ void mma16816(float* d, const unsigned* a, const unsigned* b) {
    asm volatile(
        "mma.sync.aligned.m16n8k16.row.col.f32.f16.f16.f32 "
        "{%0,%1,%2,%3}, {%4,%5,%6,%7}, {%8,%9}, {%0,%1,%2,%3};"
        : "+f"(d[0]), "+f"(d[1]), "+f"(d[2]), "+f"(d[3])
        : "r"(a[0]), "r"(a[1]), "r"(a[2]), "r"(a[3]), "r"(b[0]), "r"(b[1]));
}
// swizzled byte offset inside a tile whose rows are 64 fp16 = 128B
__device__ __forceinline__ unsigned aoff(int r, int k) {
    return (unsigned)((r << 7) + (((((k >> 3) ^ r) & 7)) << 4) + ((k & 7) << 1));
}

// ---------------- CSR construction ----------------
__global__ void zero_kernel(int n) {
    int i = blockIdx.x * blockDim.x + threadIdx.x;
    if (i < n) { g_cnt[i] = 0; g_cursor[i] = 0; }
}
__global__ void hist_kernel(const int* __restrict__ ei, int E) {
    int e = blockIdx.x * blockDim.x + threadIdx.x;
    if (e < E) atomicAdd(&g_cnt[ei[e]], 1);
}
__global__ void scan_kernel(int n) {
    __shared__ int sh[1024];
    __shared__ int carry;
    if (threadIdx.x == 0) carry = 0;
    __syncthreads();
    for (int base = 0; base < n; base += 1024) {
        int i = base + threadIdx.x;
        int v = (i < n) ? g_cnt[i] : 0;
        sh[threadIdx.x] = v;
        __syncthreads();
        for (int off = 1; off < 1024; off <<= 1) {
            int t = (threadIdx.x >= off) ? sh[threadIdx.x - off] : 0;
            __syncthreads();
            sh[threadIdx.x] += t;
            __syncthreads();
        }
        if (i < n) g_rowptr[i] = carry + sh[threadIdx.x] - v;
        __syncthreads();
        if (threadIdx.x == 0) carry += sh[1023];
        __syncthreads();
    }
    if (threadIdx.x == 0) g_rowptr[n] = carry;
}
__global__ void fill_kernel(const int* __restrict__ ei, int E) {
    int e = blockIdx.x * blockDim.x + threadIdx.x;
    if (e < E) {
        int s = ei[e];
        int d = ei[E + e];
        int p = atomicAdd(&g_cursor[s], 1);
        g_col[g_rowptr[s] + p] = d;
    }
}

// ---------------- conversions ----------------
__global__ void convert_x_kernel(const float* __restrict__ x, int n4) {
    int i = blockIdx.x * blockDim.x + threadIdx.x;
    if (i >= n4) return;
    float4 v = ((const float4*)x)[i];
    __half h0 = __float2half_rn(v.x);
    __half h1 = __float2half_rn(v.y);
    __half h2 = __float2half_rn(v.z);
    __half h3 = __float2half_rn(v.w);
    __half l0 = __float2half_rn(v.x - __half2float(h0));
    __half l1 = __float2half_rn(v.y - __half2float(h1));
    __half l2 = __float2half_rn(v.z - __half2float(h2));
    __half l3 = __float2half_rn(v.w - __half2float(h3));
    ((__half2*)g_xh)[i * 2]     = __half2(h0, h1);
    ((__half2*)g_xh)[i * 2 + 1] = __half2(h2, h3);
    ((__half2*)g_xl)[i * 2]     = __half2(l0, l1);
    ((__half2*)g_xl)[i * 2 + 1] = __half2(l2, l3);
}

__global__ void convert_w_kernel(const float* __restrict__ Ws,
                                 const float* __restrict__ muW,
                                 const float* __restrict__ lvW) {
    int i = blockIdx.x * blockDim.x + threadIdx.x;
    float v;
    __half* p;
    if (i < 512 * 512) {
        int row = i >> 9, k = i & 511;            // row = h*64 + n
        int h = row >> 6, n = row & 63;
        v = Ws[((size_t)h * 512 + k) * 64 + n];
        p = g_bt1 + i;
    } else if (i < 512 * 512 + 256 * 512) {
        int j = i - 512 * 512;
        int n = j >> 9, k = j & 511;
        v = (n < 128) ? muW[(size_t)k * 128 + n]
                      : lvW[(size_t)k * 128 + (n - 128)];
        p = g_bt2 + j;
    } else return;
    *p = __float2half_rn(v);
}

// ---------------- HMMA fp16 2-limb-A GEMM, 128x128 tile, 256 threads -------
// C[m0:+128, nb:+128] = (Ah+Al)[M,512] * Bt[nb:+128, 512]^T, fp32 accum.
// 2 MMA passes per k16: Ah*B + Al*B.
// Stage: Ah 16K | Al 16K | B 16K = 48KB; 2 stages = 96KB -> 2 CTAs/SM.
#define KC 64
#define STAGE 49152

__device__ __forceinline__ void load_chunk(
    unsigned st, const __half* __restrict__ Ah, const __half* __restrict__ Al,
    const __half* __restrict__ B, int m0, int k0, int M, int tid)
{
#pragma unroll
    for (int it = 0; it < 4; it++) {
        int idx = it * 256 + tid;
        int r = idx >> 3, c = idx & 7;
        unsigned d = st + (unsigned)((r << 7) + (((c ^ (r & 7)) & 7) << 4));
        int grow = m0 + r;
        int sz = (grow < M) ? 16 : 0;
        if (grow >= M) grow = M - 1;
        size_t go = (size_t)grow * 512 + k0 + c * 8;
        cp16(d,         Ah + go, sz);
        cp16(d + 16384, Al + go, sz);
        size_t gb = (size_t)r * 512 + k0 + c * 8;   // B pre-offset by nb rows
        cp16(d + 32768, B + gb, 16);
    }
}

__global__ __launch_bounds__(256) void gemm_tc(
    const __half* __restrict__ Ah, const __half* __restrict__ Al,
    const __half* __restrict__ Bg,
    float* __restrict__ C, int M, int ldc)
{
    extern __shared__ char smem[];
    const unsigned sbase = smem_u32(smem);
    const int tid = threadIdx.x, lane = tid & 31, wid = tid >> 5;
    const int m0 = blockIdx.y * 128;        // n fastest -> A reuse in L2
    const int nb = blockIdx.x * 128;
    C += nb;
    const __half* B = Bg + (size_t)nb * 512;
    const int wm = (wid & 3) * 32, wn = (wid >> 2) * 64;

    float acc[2][8][4];
#pragma unroll
    for (int i = 0; i < 2; i++)
#pragma unroll
        for (int j = 0; j < 8; j++)
#pragma unroll
            for (int q = 0; q < 4; q++) acc[i][j][q] = 0.f;

    load_chunk(sbase,         Ah, Al, B, m0, 0,  M, tid);
    cp_commit();
    load_chunk(sbase + STAGE, Ah, Al, B, m0, KC, M, tid);
    cp_commit();

    for (int kc = 0; kc < 8; kc++) {
        if (kc < 7)
            asm volatile("cp.async.wait_group 1;" ::: "memory");
        else
            asm volatile("cp.async.wait_group 0;" ::: "memory");
        __syncthreads();
        const unsigned st = sbase + (kc & 1) * STAGE;
#pragma unroll
        for (int kk = 0; kk < 4; kk++) {
            const int k = kk * 16;
            int ar = lane & 15;
            int ac = k + ((lane >> 4) << 3);
            unsigned ah[2][4], al[2][4];
            ldsm4(ah[0][0], ah[0][1], ah[0][2], ah[0][3], st + aoff(wm + ar, ac));
            ldsm4(ah[1][0], ah[1][1], ah[1][2], ah[1][3], st + aoff(wm + 16 + ar, ac));
            ldsm4(al[0][0], al[0][1], al[0][2], al[0][3], st + 16384 + aoff(wm + ar, ac));
            ldsm4(al[1][0], al[1][1], al[1][2], al[1][3], st + 16384 + aoff(wm + 16 + ar, ac));
            int br = (lane & 7) + ((lane >> 4) << 3);
            int bc = k + (((lane >> 3) & 1) << 3);
            unsigned b[8][2];
#pragma unroll
            for (int q = 0; q < 4; q++)
                ldsm4(b[2*q][0], b[2*q][1], b[2*q+1][0], b[2*q+1][1],
                      st + 32768 + aoff(wn + 16 * q + br, bc));
#pragma unroll
            for (int mt = 0; mt < 2; mt++)
#pragma unroll
                for (int nt = 0; nt < 8; nt++) {
                    mma16816(acc[mt][nt], ah[mt], b[nt]);
                    mma16816(acc[mt][nt], al[mt], b[nt]);
                }
        }
        __syncthreads();
        if (kc + 2 < 8) {
            load_chunk(sbase + (kc & 1) * STAGE, Ah, Al, B, m0, (kc + 2) * KC, M, tid);
            cp_commit();
        }
    }

#pragma unroll
    for (int mt = 0; mt < 2; mt++) {
        int r0 = m0 + wm + mt * 16 + (lane >> 2);
#pragma unroll
        for (int nt = 0; nt < 8; nt++) {
            int c0 = wn + nt * 8 + (lane & 3) * 2;
            if (r0 < M)
                *(float2*)&C[(size_t)r0 * ldc + c0] =
                    make_float2(acc[mt][nt][0], acc[mt][nt][1]);
            if (r0 + 8 < M)
                *(float2*)&C[(size_t)(r0 + 8) * ldc + c0] =
                    make_float2(acc[mt][nt][2], acc[mt][nt][3]);
        }
    }
}

// ---------------- layer-1 attention scalars ----------------
__global__ __launch_bounds__(256) void scalars1_kernel(const float* __restrict__ As) {
    int n = blockIdx.x;
    int w = threadIdx.x >> 5, lane = threadIdx.x & 31;
    const float* hr = g_h_all + (size_t)n * X2DIM + w * NHID;
    float v0 = hr[lane], v1 = hr[lane + 32];
    const float* a = As + w * 2 * NHID;
    float d1 = v0 * a[lane]      + v1 * a[lane + 32];
    float d2 = v0 * a[64 + lane] + v1 * a[96 + lane];
#pragma unroll
    for (int o = 16; o; o >>= 1) {
        d1 += __shfl_down_sync(0xffffffffu, d1, o);
        d2 += __shfl_down_sync(0xffffffffu, d2, o);
    }
    if (lane == 0) { g_s1[n * 8 + w] = d1; g_s2[n * 8 + w] = d2; }
}

// ---------------- layer-1 edge aggregation + elu + fp16 split --------------
__global__ __launch_bounds__(128) void agg1_kernel() {
    int n = blockIdx.x;
    int t = threadIdx.x;
    __shared__ float sh_s1[8];
    __shared__ float sh_den[8];
    __shared__ float sh_e[16 * 8];
    __shared__ int   sh_dst[16];
    if (t < 8) { sh_s1[t] = g_s1[n * 8 + t]; sh_den[t] = 0.f; }
    __syncthreads();
    int beg = g_rowptr[n], end = g_rowptr[n + 1];
    float4 acc = make_float4(0.f, 0.f, 0.f, 0.f);
    const int h = t >> 4;
    for (int eb = beg; eb < end; eb += 16) {
        int cnt = min(16, end - eb);
        if (t < cnt) sh_dst[t] = g_col[eb + t];
        __syncthreads();
        if (t < cnt * 8) {
            int le = t >> 3, hh = t & 7;
            int d = sh_dst[le];
            float logit = sh_s1[hh] + g_s2[d * 8 + hh];
            float lr = logit > 0.f ? logit : 0.2f * logit;
            float e = __expf(-lr);
            sh_e[t] = e;
            atomicAdd(&sh_den[hh], e);
        }
        __syncthreads();
        for (int le = 0; le < cnt; le++) {
            int d = sh_dst[le];
            float w = sh_e[le * 8 + h];
            float4 v = *(const float4*)(g_h_all + (size_t)d * X2DIM + t * 4);
            acc.x += w * v.x; acc.y += w * v.y;
            acc.z += w * v.z; acc.w += w * v.w;
        }
        __syncthreads();
    }
    float inv = 1.f / sh_den[h];
    float v0 = acc.x * inv, v1 = acc.y * inv, v2 = acc.z * inv, v3 = acc.w * inv;
    v0 = v0 > 0.f ? v0 : expm1f(v0);
    v1 = v1 > 0.f ? v1 : expm1f(v1);
    v2 = v2 > 0.f ? v2 : expm1f(v2);
    v3 = v3 > 0.f ? v3 : expm1f(v3);
    __half h0 = __float2half_rn(v0);
    __half h1 = __float2half_rn(v1);
    __half h2 = __float2half_rn(v2);
    __half h3 = __float2half_rn(v3);
    __half l0 = __float2half_rn(v0 - __half2float(h0));
    __half l1 = __float2half_rn(v1 - __half2float(h1));
    __half l2 = __float2half_rn(v2 - __half2float(h2));
    __half l3 = __float2half_rn(v3 - __half2float(h3));
    size_t o = (size_t)n * X2DIM + t * 4;
    ((__half2*)(g_x2h + o))[0] = __half2(h0, h1);
    ((__half2*)(g_x2h + o))[1] = __half2(h2, h3);
    ((__half2*)(g_x2l + o))[0] = __half2(l0, l1);
    ((__half2*)(g_x2l + o))[1] = __half2(l2, l3);
}

// ---------------- layer-2 attention scalars ----------------
__global__ __launch_bounds__(128) void scalars2_kernel(
    const float* __restrict__ mua, const float* __restrict__ lva)
{
    int n = blockIdx.x, t = threadIdx.x;
    float hmu = g_hml[(size_t)n * 256 + t];
    float hlv = g_hml[(size_t)n * 256 + 128 + t];
    float p0 = hmu * mua[t];
    float p1 = hmu * mua[128 + t];
    float p2 = hlv * lva[t];
    float p3 = hlv * lva[128 + t];
#pragma unroll
    for (int o = 16; o; o >>= 1) {
        p0 += __shfl_down_sync(0xffffffffu, p0, o);
        p1 += __shfl_down_sync(0xffffffffu, p1, o);
        p2 += __shfl_down_sync(0xffffffffu, p2, o);
        p3 += __shfl_down_sync(0xffffffffu, p3, o);
    }
    __shared__ float red[4][4];
    int w = t >> 5, lane = t & 31;
    if (lane == 0) { red[w][0] = p0; red[w][1] = p1; red[w][2] = p2; red[w][3] = p3; }
    __syncthreads();
    if (t == 0) {
        g_smu1[n] = red[0][0] + red[1][0] + red[2][0] + red[3][0];
        g_smu2[n] = red[0][1] + red[1][1] + red[2][1] + red[3][1];
        g_slv1[n] = red[0][2] + red[1][2] + red[2][2] + red[3][2];
        g_slv2[n] = red[0][3] + red[1][3] + red[2][3] + red[3][3];
    }
}

// ---------------- layer-2 edge aggregation + reparameterize ----------------
__global__ __launch_bounds__(128) void agg2_kernel(
    const float* __restrict__ eps, float* __restrict__ out, int n_total)
{
    int n = blockIdx.x, t = threadIdx.x;
    __shared__ float sh_w[2][32];
    __shared__ int   sh_dst[32];
    __shared__ float sden[2];
    __shared__ float sval[256];
    if (t < 2) sden[t] = 0.f;
    float base_mu = g_smu1[n];
    float base_lv = g_slv1[n];
    __syncthreads();
    int beg = g_rowptr[n], end = g_rowptr[n + 1];
    const int sel = t >> 6;
    float2 acc = make_float2(0.f, 0.f);
    for (int eb = beg; eb < end; eb += 32) {
        int cnt = min(32, end - eb);
        if (t < cnt) {
            int d = g_col[eb + t];
            sh_dst[t] = d;
            float lmu = base_mu + g_smu2[d];
            float llv = base_lv + g_slv2[d];
            lmu = lmu > 0.f ? lmu : 0.2f * lmu;
            llv = llv > 0.f ? llv : 0.2f * llv;
            float emu = __expf(-lmu);
            float elv = __expf(-llv);
            sh_w[0][t] = emu; sh_w[1][t] = elv;
            atomicAdd(&sden[0], emu);
            atomicAdd(&sden[1], elv);
        }
        __syncthreads();
        for (int le = 0; le < cnt; le++) {
            int d = sh_dst[le];
            float w = sh_w[sel][le];
            float2 v = *(const float2*)(g_hml + (size_t)d * 256 + 2 * t);
            acc.x += w * v.x;
            acc.y += w * v.y;
        }
        __syncthreads();
    }
    float inv = 1.f / sden[sel];
    sval[2 * t]     = acc.x * inv;
    sval[2 * t + 1] = acc.y * inv;
    __syncthreads();
    float mu = sval[t];
    float lv = sval[128 + t];
    float z  = eps[(size_t)n * NOUT + t] * expf(lv) + mu;
    size_t NO = (size_t)n_total * NOUT;
    out[(size_t)n * NOUT + t]          = z;
    out[NO + (size_t)n * NOUT + t]     = mu;
    out[2 * NO + (size_t)n * NOUT + t] = lv;
}

// ---------------- host orchestration ----------------
extern "C" void kernel_launch(void* const* d_in, const int* in_sizes, int n_in,
                              void* d_out, int out_size)
{
    const float* x   = (const float*)d_in[0];
    const float* Ws  = (const float*)d_in[1];
    const float* As  = (const float*)d_in[2];
    const float* muW = (const float*)d_in[3];
    const float* mua = (const float*)d_in[4];
    const float* lvW = (const float*)d_in[5];
    const float* lva = (const float*)d_in[6];
    const float* eps = (const float*)d_in[7];
    const int*   ei  = (const int*)d_in[8];
    int E = in_sizes[8] / 2;
    int N = in_sizes[0] / NFEAT;
    float* out = (float*)d_out;

    float *p_hall, *p_hml;
    __half *p_xh, *p_xl, *p_x2h, *p_x2l, *p_bt1, *p_bt2;
    cudaGetSymbolAddress((void**)&p_hall, g_h_all);
    cudaGetSymbolAddress((void**)&p_hml,  g_hml);
    cudaGetSymbolAddress((void**)&p_xh,   g_xh);
    cudaGetSymbolAddress((void**)&p_xl,   g_xl);
    cudaGetSymbolAddress((void**)&p_x2h,  g_x2h);
    cudaGetSymbolAddress((void**)&p_x2l,  g_x2l);
    cudaGetSymbolAddress((void**)&p_bt1,  g_bt1);
    cudaGetSymbolAddress((void**)&p_bt2,  g_bt2);

    cudaFuncSetAttribute(gemm_tc, cudaFuncAttributeMaxDynamicSharedMemorySize,
                         2 * STAGE);

    int mtiles = (N + 127) / 128;

    // gemm_tc (layer-1) kept at the ncu-profiled launch slot (#3)
    convert_x_kernel<<<(N * NFEAT / 4 + 255) / 256, 256>>>(x, N * NFEAT / 4);     // 0
    convert_w_kernel<<<(512 * 512 + 256 * 512 + 255) / 256, 256>>>(Ws, muW, lvW); // 1
    zero_kernel<<<(N + 255) / 256, 256>>>(N);                                     // 2
    gemm_tc<<<dim3(4, mtiles), 256, 2 * STAGE>>>(p_xh, p_xl, p_bt1,               // 3
                                                 p_hall, N, X2DIM);
    hist_kernel<<<(E + 255) / 256, 256>>>(ei, E);                                 // 4
    scan_kernel<<<1, 1024>>>(N);                                                  // 5
    fill_kernel<<<(E + 255) / 256, 256>>>(ei, E);                                 // 6
    scalars1_kernel<<<N, 256>>>(As);                                              // 7
    agg1_kernel<<<N, 128>>>();                                                    // 8
    gemm_tc<<<dim3(2, mtiles), 256, 2 * STAGE>>>(p_x2h, p_x2l, p_bt2,             // 9
                                                 p_hml, N, 256);
    scalars2_kernel<<<N, 128>>>(mua, lva);                                        // 10
    agg2_kernel<<<N, 128>>>(eps, out, N);                                         // 11
}

// round 8
// speedup vs baseline: 1.2836x; 1.0155x over previous
#include <cuda_runtime.h>
#include <cuda_fp16.h>
#include <cstdint>

// ---------------- problem constants ----------------
#define N_NODES  50000
#define E_MAX    450000
#define NFEAT    512
#define NHID     64
#define NHEADS   8
#define NOUT     128
#define X2DIM    512

// ---------------- device scratch ----------------
__device__ float g_h_all[(size_t)N_NODES * X2DIM];
__device__ float g_s1  [N_NODES * NHEADS];
__device__ float g_s2  [N_NODES * NHEADS];
__device__ float g_hml [(size_t)N_NODES * 256];     // [:,0:128]=h_mu, [:,128:256]=h_lv
__device__ float g_smu1[N_NODES], g_smu2[N_NODES], g_slv1[N_NODES], g_slv2[N_NODES];
__device__ int   g_rowptr[N_NODES + 1];
__device__ int   g_col [E_MAX];
__device__ int   g_cnt [N_NODES];
__device__ int   g_cursor[N_NODES];

// fp16 2-limb activations, fp16 1-limb weights
__device__ __half g_xh [(size_t)N_NODES * NFEAT];
__device__ __half g_xl [(size_t)N_NODES * NFEAT];
__device__ __half g_x2h[(size_t)N_NODES * X2DIM];
__device__ __half g_x2l[(size_t)N_NODES * X2DIM];
__device__ __half g_bt1[512 * 512];                 // Ws^T        [512,512]
__device__ __half g_bt2[256 * 512];                 // [muW;lvW]^T [256,512]

// ---------------- PTX helpers (target-generic, sm_80+) ----------------
__device__ __forceinline__ unsigned smem_u32(const void* p) {
    unsigned r;
    asm("{ .reg .u64 t; cvta.to.shared.u64 t, %1; cvt.u32.u64 %0, t; }"
        : "=r"(r) : "l"(p));
    return r;
}
__device__ __forceinline__ void cp16(unsigned dst, const void* src, int srcsz) {
    asm volatile("cp.async.cg.shared.global [%0], [%1], 16, %2;"
                 :: "r"(dst), "l"(src), "r"(srcsz) : "memory");
}
__device__ __forceinline__ void cp_commit() {
    asm volatile("cp.async.commit_group;" ::: "memory");
}
__device__ __forceinline__ void ldsm4(unsigned& r0, unsigned& r1, unsigned& r2,
                                      unsigned& r3, unsigned a) {
    asm volatile("ldmatrix.sync.aligned.m8n8.x4.shared.b16 {%0,%1,%2,%3}, [%4];"
                 : "=r"(r0), "=r"(r1), "=r"(r2), "=r"(r3) : "r"(a));
}
__device__ __forceinline__ void mma16816(float* d, const unsigned* a, const unsigned* b) {
    asm volatile(
        "mma.sync.aligned.m16n8k16.row.col.f32.f16.f16.f32 "
        "{%0,%1,%2,%3}, {%4,%5,%6,%7}, {%8,%9}, {%0,%1,%2,%3};"
        : "+f"(d[0]), "+f"(d[1]), "+f"(d[2]), "+f"(d[3])
        : "r"(a[0]), "r"(a[1]), "r"(a[2]), "r"(a[3]), "r"(b[0]), "r"(b[1]));
}
// swizzled byte offset inside a tile whose rows are 64 fp16 = 128B
__device__ __forceinline__ unsigned aoff(int r, int k) {
    return (unsigned)((r << 7) + (((((k >> 3) ^ r) & 7)) << 4) + ((k & 7) << 1));
}

// ---------------- CSR construction ----------------
__global__ void zero_kernel(int n) {
    int i = blockIdx.x * blockDim.x + threadIdx.x;
    if (i < n) { g_cnt[i] = 0; g_cursor[i] = 0; }
}
__global__ void hist_kernel(const int* __restrict__ ei, int E) {
    int e = blockIdx.x * blockDim.x + threadIdx.x;
    if (e < E) atomicAdd(&g_cnt[ei[e]], 1);
}
__global__ void scan_kernel(int n) {
    __shared__ int sh[1024];
    __shared__ int carry;
    if (threadIdx.x == 0) carry = 0;
    __syncthreads();
    for (int base = 0; base < n; base += 1024) {
        int i = base + threadIdx.x;
        int v = (i < n) ? g_cnt[i] : 0;
        sh[threadIdx.x] = v;
        __syncthreads();
        for (int off = 1; off < 1024; off <<= 1) {
            int t = (threadIdx.x >= off) ? sh[threadIdx.x - off] : 0;
            __syncthreads();
            sh[threadIdx.x] += t;
            __syncthreads();
        }
        if (i < n) g_rowptr[i] = carry + sh[threadIdx.x] - v;
        __syncthreads();
        if (threadIdx.x == 0) carry += sh[1023];
        __syncthreads();
    }
    if (threadIdx.x == 0) g_rowptr[n] = carry;
}
__global__ void fill_kernel(const int* __restrict__ ei, int E) {
    int e = blockIdx.x * blockDim.x + threadIdx.x;
    if (e < E) {
        int s = ei[e];
        int d = ei[E + e];
        int p = atomicAdd(&g_cursor[s], 1);
        g_col[g_rowptr[s] + p] = d;
    }
}

// ---------------- conversions ----------------
__global__ void convert_x_kernel(const float* __restrict__ x, int n4) {
    int i = blockIdx.x * blockDim.x + threadIdx.x;
    if (i >= n4) return;
    float4 v = ((const float4*)x)[i];
    __half h0 = __float2half_rn(v.x);
    __half h1 = __float2half_rn(v.y);
    __half h2 = __float2half_rn(v.z);
    __half h3 = __float2half_rn(v.w);
    __half l0 = __float2half_rn(v.x - __half2float(h0));
    __half l1 = __float2half_rn(v.y - __half2float(h1));
    __half l2 = __float2half_rn(v.z - __half2float(h2));
    __half l3 = __float2half_rn(v.w - __half2float(h3));
    ((__half2*)g_xh)[i * 2]     = __half2(h0, h1);
    ((__half2*)g_xh)[i * 2 + 1] = __half2(h2, h3);
    ((__half2*)g_xl)[i * 2]     = __half2(l0, l1);
    ((__half2*)g_xl)[i * 2 + 1] = __half2(l2, l3);
}

__global__ void convert_w_kernel(const float* __restrict__ Ws,
                                 const float* __restrict__ muW,
                                 const float* __restrict__ lvW) {
    int i = blockIdx.x * blockDim.x + threadIdx.x;
    float v;
    __half* p;
    if (i < 512 * 512) {
        int row = i >> 9, k = i & 511;            // row = h*64 + n
        int h = row >> 6, n = row & 63;
        v = Ws[((size_t)h * 512 + k) * 64 + n];
        p = g_bt1 + i;
    } else if (i < 512 * 512 + 256 * 512) {
        int j = i - 512 * 512;
        int n = j >> 9, k = j & 511;
        v = (n < 128) ? muW[(size_t)k * 128 + n]
                      : lvW[(size_t)k * 128 + (n - 128)];
        p = g_bt2 + j;
    } else return;
    *p = __float2half_rn(v);
}

// ---------------- HMMA fp16 2-limb-A GEMM (unchanged from R7) ---------------
#define KC 64
#define STAGE 49152

__device__ __forceinline__ void load_chunk(
    unsigned st, const __half* __restrict__ Ah, const __half* __restrict__ Al,
    const __half* __restrict__ B, int m0, int k0, int M, int tid)
{
#pragma unroll
    for (int it = 0; it < 4; it++) {
        int idx = it * 256 + tid;
        int r = idx >> 3, c = idx & 7;
        unsigned d = st + (unsigned)((r << 7) + (((c ^ (r & 7)) & 7) << 4));
        int grow = m0 + r;
        int sz = (grow < M) ? 16 : 0;
        if (grow >= M) grow = M - 1;
        size_t go = (size_t)grow * 512 + k0 + c * 8;
        cp16(d,         Ah + go, sz);
        cp16(d + 16384, Al + go, sz);
        size_t gb = (size_t)r * 512 + k0 + c * 8;   // B pre-offset by nb rows
        cp16(d + 32768, B + gb, 16);
    }
}

__global__ __launch_bounds__(256) void gemm_tc(
    const __half* __restrict__ Ah, const __half* __restrict__ Al,
    const __half* __restrict__ Bg,
    float* __restrict__ C, int M, int ldc)
{
    extern __shared__ char smem[];
    const unsigned sbase = smem_u32(smem);
    const int tid = threadIdx.x, lane = tid & 31, wid = tid >> 5;
    const int m0 = blockIdx.y * 128;
    const int nb = blockIdx.x * 128;
    C += nb;
    const __half* B = Bg + (size_t)nb * 512;
    const int wm = (wid & 3) * 32, wn = (wid >> 2) * 64;

    float acc[2][8][4];
#pragma unroll
    for (int i = 0; i < 2; i++)
#pragma unroll
        for (int j = 0; j < 8; j++)
#pragma unroll
            for (int q = 0; q < 4; q++) acc[i][j][q] = 0.f;

    load_chunk(sbase,         Ah, Al, B, m0, 0,  M, tid);
    cp_commit();
    load_chunk(sbase + STAGE, Ah, Al, B, m0, KC, M, tid);
    cp_commit();

    for (int kc = 0; kc < 8; kc++) {
        if (kc < 7)
            asm volatile("cp.async.wait_group 1;" ::: "memory");
        else
            asm volatile("cp.async.wait_group 0;" ::: "memory");
        __syncthreads();
        const unsigned st = sbase + (kc & 1) * STAGE;
#pragma unroll
        for (int kk = 0; kk < 4; kk++) {
            const int k = kk * 16;
            int ar = lane & 15;
            int ac = k + ((lane >> 4) << 3);
            unsigned ah[2][4], al[2][4];
            ldsm4(ah[0][0], ah[0][1], ah[0][2], ah[0][3], st + aoff(wm + ar, ac));
            ldsm4(ah[1][0], ah[1][1], ah[1][2], ah[1][3], st + aoff(wm + 16 + ar, ac));
            ldsm4(al[0][0], al[0][1], al[0][2], al[0][3], st + 16384 + aoff(wm + ar, ac));
            ldsm4(al[1][0], al[1][1], al[1][2], al[1][3], st + 16384 + aoff(wm + 16 + ar, ac));
            int br = (lane & 7) + ((lane >> 4) << 3);
            int bc = k + (((lane >> 3) & 1) << 3);
            unsigned b[8][2];
#pragma unroll
            for (int q = 0; q < 4; q++)
                ldsm4(b[2*q][0], b[2*q][1], b[2*q+1][0], b[2*q+1][1],
                      st + 32768 + aoff(wn + 16 * q + br, bc));
#pragma unroll
            for (int mt = 0; mt < 2; mt++)
#pragma unroll
                for (int nt = 0; nt < 8; nt++) {
                    mma16816(acc[mt][nt], ah[mt], b[nt]);
                    mma16816(acc[mt][nt], al[mt], b[nt]);
                }
        }
        __syncthreads();
        if (kc + 2 < 8) {
            load_chunk(sbase + (kc & 1) * STAGE, Ah, Al, B, m0, (kc + 2) * KC, M, tid);
            cp_commit();
        }
    }

#pragma unroll
    for (int mt = 0; mt < 2; mt++) {
        int r0 = m0 + wm + mt * 16 + (lane >> 2);
#pragma unroll
        for (int nt = 0; nt < 8; nt++) {
            int c0 = wn + nt * 8 + (lane & 3) * 2;
            if (r0 < M)
                *(float2*)&C[(size_t)r0 * ldc + c0] =
                    make_float2(acc[mt][nt][0], acc[mt][nt][1]);
            if (r0 + 8 < M)
                *(float2*)&C[(size_t)(r0 + 8) * ldc + c0] =
                    make_float2(acc[mt][nt][2], acc[mt][nt][3]);
        }
    }
}

// ---------------- layer-1 attention scalars ----------------
__global__ __launch_bounds__(256) void scalars1_kernel(const float* __restrict__ As) {
    int n = blockIdx.x;
    int w = threadIdx.x >> 5, lane = threadIdx.x & 31;
    const float* hr = g_h_all + (size_t)n * X2DIM + w * NHID;
    float v0 = hr[lane], v1 = hr[lane + 32];
    const float* a = As + w * 2 * NHID;
    float d1 = v0 * a[lane]      + v1 * a[lane + 32];
    float d2 = v0 * a[64 + lane] + v1 * a[96 + lane];
#pragma unroll
    for (int o = 16; o; o >>= 1) {
        d1 += __shfl_down_sync(0xffffffffu, d1, o);
        d2 += __shfl_down_sync(0xffffffffu, d2, o);
    }
    if (lane == 0) { g_s1[n * 8 + w] = d1; g_s2[n * 8 + w] = d2; }
}

// ---------------- layer-1 aggregation: warp-per-node, no smem/barriers -----
__device__ __forceinline__ void fma4(float4& a, float w, const float4& v) {
    a.x += w * v.x; a.y += w * v.y; a.z += w * v.z; a.w += w * v.w;
}

__global__ __launch_bounds__(256) void agg1_kernel(int N) {
    int n = (blockIdx.x * 256 + threadIdx.x) >> 5;
    if (n >= N) return;
    const int lane = threadIdx.x & 31;
    const int le = lane >> 3, hh = lane & 7;   // weight phase: edge-in-4, head
    const int hme = lane >> 2;                 // my head for gather/denominator
    const int beg = g_rowptr[n];
    const int deg = g_rowptr[n + 1] - beg;

    const float s1v = g_s1[n * 8 + hh];
    float4 a0 = make_float4(0,0,0,0), a1 = a0, a2 = a0, a3 = a0;
    float den = 0.f;

    for (int eb = 0; eb < deg; eb += 4) {
        const int cnt = min(4, deg - eb);
        int d_le = g_col[beg + ((le < cnt) ? (eb + le) : 0)];
        float logit = s1v + g_s2[d_le * 8 + hh];
        float lr = logit > 0.f ? logit : 0.2f * logit;
        float w_le = __expf(-lr);
#pragma unroll 4
        for (int e = 0; e < cnt; e++) {
            int   d = __shfl_sync(0xffffffffu, d_le, e << 3);
            float w = __shfl_sync(0xffffffffu, w_le, (e << 3) + hme);
            const float4* hr = (const float4*)(g_h_all + (size_t)d * X2DIM) + lane * 4;
            fma4(a0, w, hr[0]); fma4(a1, w, hr[1]);
            fma4(a2, w, hr[2]); fma4(a3, w, hr[3]);
            den += w;
        }
    }

    const float inv = 1.f / den;
    float v[16];
    v[0]=a0.x; v[1]=a0.y; v[2]=a0.z; v[3]=a0.w;
    v[4]=a1.x; v[5]=a1.y; v[6]=a1.z; v[7]=a1.w;
    v[8]=a2.x; v[9]=a2.y; v[10]=a2.z; v[11]=a2.w;
    v[12]=a3.x; v[13]=a3.y; v[14]=a3.z; v[15]=a3.w;
    __half hi[16], lo[16];
#pragma unroll
    for (int i = 0; i < 16; i++) {
        float t = v[i] * inv;
        t = t > 0.f ? t : expm1f(t);
        __half h = __float2half_rn(t);
        hi[i] = h;
        lo[i] = __float2half_rn(t - __half2float(h));
    }
    size_t o = (size_t)n * X2DIM + lane * 16;
    ((uint4*)(g_x2h + o))[0] = *(uint4*)(hi);
    ((uint4*)(g_x2h + o))[1] = *(uint4*)(hi + 8);
    ((uint4*)(g_x2l + o))[0] = *(uint4*)(lo);
    ((uint4*)(g_x2l + o))[1] = *(uint4*)(lo + 8);
}

// ---------------- layer-2 attention scalars ----------------
__global__ __launch_bounds__(128) void scalars2_kernel(
    const float* __restrict__ mua, const float* __restrict__ lva)
{
    int n = blockIdx.x, t = threadIdx.x;
    float hmu = g_hml[(size_t)n * 256 + t];
    float hlv = g_hml[(size_t)n * 256 + 128 + t];
    float p0 = hmu * mua[t];
    float p1 = hmu * mua[128 + t];
    float p2 = hlv * lva[t];
    float p3 = hlv * lva[128 + t];
#pragma unroll
    for (int o = 16; o; o >>= 1) {
        p0 += __shfl_down_sync(0xffffffffu, p0, o);
        p1 += __shfl_down_sync(0xffffffffu, p1, o);
        p2 += __shfl_down_sync(0xffffffffu, p2, o);
        p3 += __shfl_down_sync(0xffffffffu, p3, o);
    }
    __shared__ float red[4][4];
    int w = t >> 5, lane = t & 31;
    if (lane == 0) { red[w][0] = p0; red[w][1] = p1; red[w][2] = p2; red[w][3] = p3; }
    __syncthreads();
    if (t == 0) {
        g_smu1[n] = red[0][0] + red[1][0] + red[2][0] + red[3][0];
        g_smu2[n] = red[0][1] + red[1][1] + red[2][1] + red[3][1];
        g_slv1[n] = red[0][2] + red[1][2] + red[2][2] + red[3][2];
        g_slv2[n] = red[0][3] + red[1][3] + red[2][3] + red[3][3];
    }
}

// ---------------- layer-2 aggregation: warp-per-node + reparameterize ------
__global__ __launch_bounds__(256) void agg2_kernel(
    const float* __restrict__ eps, float* __restrict__ out, int N)
{
    int n = (blockIdx.x * 256 + threadIdx.x) >> 5;
    if (n >= N) return;
    const int lane = threadIdx.x & 31;
    const int beg = g_rowptr[n];
    const int deg = g_rowptr[n + 1] - beg;
    const float bmu = g_smu1[n], blv = g_slv1[n];

    float4 amu = make_float4(0,0,0,0), alv = amu;
    float dmu = 0.f, dlv = 0.f;

    for (int eb = 0; eb < deg; eb += 32) {
        const int cnt = min(32, deg - eb);
        int d_l = g_col[beg + ((lane < cnt) ? (eb + lane) : 0)];
        float lmu = bmu + g_smu2[d_l];
        float llv = blv + g_slv2[d_l];
        lmu = lmu > 0.f ? lmu : 0.2f * lmu;
        llv = llv > 0.f ? llv : 0.2f * llv;
        float wmu_l = __expf(-lmu);
        float wlv_l = __expf(-llv);
#pragma unroll 4
        for (int e = 0; e < cnt; e++) {
            int   d   = __shfl_sync(0xffffffffu, d_l,   e);
            float wmu = __shfl_sync(0xffffffffu, wmu_l, e);
            float wlv = __shfl_sync(0xffffffffu, wlv_l, e);
            const float4* pm = (const float4*)(g_hml + (size_t)d * 256) + lane;
            fma4(amu, wmu, pm[0]);
            fma4(alv, wlv, pm[32]);
            dmu += wmu; dlv += wlv;
        }
    }

    const float imu = 1.f / dmu, ilv = 1.f / dlv;
    float4 mu = make_float4(amu.x*imu, amu.y*imu, amu.z*imu, amu.w*imu);
    float4 lv = make_float4(alv.x*ilv, alv.y*ilv, alv.z*ilv, alv.w*ilv);
    float4 ev = *(const float4*)(eps + (size_t)n * NOUT + lane * 4);
    float4 z  = make_float4(ev.x * expf(lv.x) + mu.x,
                            ev.y * expf(lv.y) + mu.y,
                            ev.z * expf(lv.z) + mu.z,
                            ev.w * expf(lv.w) + mu.w);
    size_t NO = (size_t)N * NOUT;
    size_t o  = (size_t)n * NOUT + lane * 4;
    *(float4*)(out + o)          = z;
    *(float4*)(out + NO + o)     = mu;
    *(float4*)(out + 2 * NO + o) = lv;
}

// ---------------- host orchestration ----------------
extern "C" void kernel_launch(void* const* d_in, const int* in_sizes, int n_in,
                              void* d_out, int out_size)
{
    const float* x   = (const float*)d_in[0];
    const float* Ws  = (const float*)d_in[1];
    const float* As  = (const float*)d_in[2];
    const float* muW = (const float*)d_in[3];
    const float* mua = (const float*)d_in[4];
    const float* lvW = (const float*)d_in[5];
    const float* lva = (const float*)d_in[6];
    const float* eps = (const float*)d_in[7];
    const int*   ei  = (const int*)d_in[8];
    int E = in_sizes[8] / 2;
    int N = in_sizes[0] / NFEAT;
    float* out = (float*)d_out;

    float *p_hall, *p_hml;
    __half *p_xh, *p_xl, *p_x2h, *p_x2l, *p_bt1, *p_bt2;
    cudaGetSymbolAddress((void**)&p_hall, g_h_all);
    cudaGetSymbolAddress((void**)&p_hml,  g_hml);
    cudaGetSymbolAddress((void**)&p_xh,   g_xh);
    cudaGetSymbolAddress((void**)&p_xl,   g_xl);
    cudaGetSymbolAddress((void**)&p_x2h,  g_x2h);
    cudaGetSymbolAddress((void**)&p_x2l,  g_x2l);
    cudaGetSymbolAddress((void**)&p_bt1,  g_bt1);
    cudaGetSymbolAddress((void**)&p_bt2,  g_bt2);

    cudaFuncSetAttribute(gemm_tc, cudaFuncAttributeMaxDynamicSharedMemorySize,
                         2 * STAGE);

    int mtiles = (N + 127) / 128;
    int wblocks = (N + 7) / 8;     // warp-per-node kernels: 8 warps/block

    // gemm_tc (layer-1) kept at the ncu-profiled launch slot (#3)
    convert_x_kernel<<<(N * NFEAT / 4 + 255) / 256, 256>>>(x, N * NFEAT / 4);     // 0
    convert_w_kernel<<<(512 * 512 + 256 * 512 + 255) / 256, 256>>>(Ws, muW, lvW); // 1
    zero_kernel<<<(N + 255) / 256, 256>>>(N);                                     // 2
    gemm_tc<<<dim3(4, mtiles), 256, 2 * STAGE>>>(p_xh, p_xl, p_bt1,               // 3
                                                 p_hall, N, X2DIM);
    hist_kernel<<<(E + 255) / 256, 256>>>(ei, E);                                 // 4
    scan_kernel<<<1, 1024>>>(N);                                                  // 5
    fill_kernel<<<(E + 255) / 256, 256>>>(ei, E);                                 // 6
    scalars1_kernel<<<N, 256>>>(As);                                              // 7
    agg1_kernel<<<wblocks, 256>>>(N);                                             // 8
    gemm_tc<<<dim3(2, mtiles), 256, 2 * STAGE>>>(p_x2h, p_x2l, p_bt2,             // 9
                                                 p_hml, N, 256);
    scalars2_kernel<<<N, 128>>>(mua, lva);                                        // 10
    agg2_kernel<<<wblocks, 256>>>(eps, out, N);                                   // 11
}

// round 9
// speedup vs baseline: 1.4411x; 1.1227x over previous
#include <cuda_runtime.h>
#include <cuda_fp16.h>
#include <cstdint>

// ---------------- problem constants ----------------
#define N_NODES  50000
#define E_MAX    450000
#define NFEAT    512
#define NHID     64
#define NHEADS   8
#define NOUT     128
#define X2DIM    512

// ---------------- device scratch ----------------
__device__ __half g_hh [(size_t)N_NODES * X2DIM];   // layer-1 head features, fp16
__device__ float g_s1  [N_NODES * NHEADS];
__device__ float g_s2  [N_NODES * NHEADS];
__device__ float g_hml [(size_t)N_NODES * 256];     // [:,0:128]=h_mu, [:,128:256]=h_lv
__device__ float g_smu1[N_NODES], g_smu2[N_NODES], g_slv1[N_NODES], g_slv2[N_NODES];
__device__ int   g_rowptr[N_NODES + 1];
__device__ int   g_col [E_MAX];
__device__ int   g_cnt [N_NODES];
__device__ int   g_cursor[N_NODES];

// fp16 2-limb activations, fp16 1-limb weights
__device__ __half g_xh [(size_t)N_NODES * NFEAT];
__device__ __half g_xl [(size_t)N_NODES * NFEAT];
__device__ __half g_x2h[(size_t)N_NODES * X2DIM];
__device__ __half g_x2l[(size_t)N_NODES * X2DIM];
__device__ __half g_bt1[512 * 512];                 // Ws^T        [512,512]
__device__ __half g_bt2[256 * 512];                 // [muW;lvW]^T [256,512]

// ---------------- PTX helpers (target-generic, sm_80+) ----------------
__device__ __forceinline__ unsigned smem_u32(const void* p) {
    unsigned r;
    asm("{ .reg .u64 t; cvta.to.shared.u64 t, %1; cvt.u32.u64 %0, t; }"
        : "=r"(r) : "l"(p));
    return r;
}
__device__ __forceinline__ void cp16(unsigned dst, const void* src, int srcsz) {
    asm volatile("cp.async.cg.shared.global [%0], [%1], 16, %2;"
                 :: "r"(dst), "l"(src), "r"(srcsz) : "memory");
}
__device__ __forceinline__ void cp_commit() {
    asm volatile("cp.async.commit_group;" ::: "memory");
}
__device__ __forceinline__ void ldsm4(unsigned& r0, unsigned& r1, unsigned& r2,
                                      unsigned& r3, unsigned a) {
    asm volatile("ldmatrix.sync.aligned.m8n8.x4.shared.b16 {%0,%1,%2,%3}, [%4];"
                 : "=r"(r0), "=r"(r1), "=r"(r2), "=r"(r3) : "r"(a));
}
__device__ __forceinline__ void mma16816(float* d, const unsigned* a, const unsigned* b) {
    asm volatile(
        "mma.sync.aligned.m16n8k16.row.col.f32.f16.f16.f32 "
        "{%0,%1,%2,%3}, {%4,%5,%6,%7}, {%8,%9}, {%0,%1,%2,%3};"
        : "+f"(d[0]), "+f"(d[1]), "+f"(d[2]), "+f"(d[3])
        : "r"(a[0]), "r"(a[1]), "r"(a[2]), "r"(a[3]), "r"(b[0]), "r"(b[1]));
}
// swizzled byte offset inside a tile whose rows are 64 fp16 = 128B
__device__ __forceinline__ unsigned aoff(int r, int k) {
    return (unsigned)((r << 7) + (((((k >> 3) ^ r) & 7)) << 4) + ((k & 7) << 1));
}

// ---------------- CSR construction ----------------
__global__ void zero_kernel(int n) {
    int i = blockIdx.x * blockDim.x + threadIdx.x;
    if (i < n) { g_cnt[i] = 0; g_cursor[i] = 0; }
}
__global__ void hist_kernel(const int* __restrict__ ei, int E) {
    int e = blockIdx.x * blockDim.x + threadIdx.x;
    if (e < E) atomicAdd(&g_cnt[ei[e]], 1);
}
__global__ void scan_kernel(int n) {
    __shared__ int sh[1024];
    __shared__ int carry;
    if (threadIdx.x == 0) carry = 0;
    __syncthreads();
    for (int base = 0; base < n; base += 1024) {
        int i = base + threadIdx.x;
        int v = (i < n) ? g_cnt[i] : 0;
        sh[threadIdx.x] = v;
        __syncthreads();
        for (int off = 1; off < 1024; off <<= 1) {
            int t = (threadIdx.x >= off) ? sh[threadIdx.x - off] : 0;
            __syncthreads();
            sh[threadIdx.x] += t;
            __syncthreads();
        }
        if (i < n) g_rowptr[i] = carry + sh[threadIdx.x] - v;
        __syncthreads();
        if (threadIdx.x == 0) carry += sh[1023];
        __syncthreads();
    }
    if (threadIdx.x == 0) g_rowptr[n] = carry;
}
__global__ void fill_kernel(const int* __restrict__ ei, int E) {
    int e = blockIdx.x * blockDim.x + threadIdx.x;
    if (e < E) {
        int s = ei[e];
        int d = ei[E + e];
        int p = atomicAdd(&g_cursor[s], 1);
        g_col[g_rowptr[s] + p] = d;
    }
}

// ---------------- conversions ----------------
__global__ void convert_x_kernel(const float* __restrict__ x, int n4) {
    int i = blockIdx.x * blockDim.x + threadIdx.x;
    if (i >= n4) return;
    float4 v = ((const float4*)x)[i];
    __half h0 = __float2half_rn(v.x);
    __half h1 = __float2half_rn(v.y);
    __half h2 = __float2half_rn(v.z);
    __half h3 = __float2half_rn(v.w);
    __half l0 = __float2half_rn(v.x - __half2float(h0));
    __half l1 = __float2half_rn(v.y - __half2float(h1));
    __half l2 = __float2half_rn(v.z - __half2float(h2));
    __half l3 = __float2half_rn(v.w - __half2float(h3));
    ((__half2*)g_xh)[i * 2]     = __half2(h0, h1);
    ((__half2*)g_xh)[i * 2 + 1] = __half2(h2, h3);
    ((__half2*)g_xl)[i * 2]     = __half2(l0, l1);
    ((__half2*)g_xl)[i * 2 + 1] = __half2(l2, l3);
}

__global__ void convert_w_kernel(const float* __restrict__ Ws,
                                 const float* __restrict__ muW,
                                 const float* __restrict__ lvW) {
    int i = blockIdx.x * blockDim.x + threadIdx.x;
    float v;
    __half* p;
    if (i < 512 * 512) {
        int row = i >> 9, k = i & 511;            // row = h*64 + n
        int h = row >> 6, n = row & 63;
        v = Ws[((size_t)h * 512 + k) * 64 + n];
        p = g_bt1 + i;
    } else if (i < 512 * 512 + 256 * 512) {
        int j = i - 512 * 512;
        int n = j >> 9, k = j & 511;
        v = (n < 128) ? muW[(size_t)k * 128 + n]
                      : lvW[(size_t)k * 128 + (n - 128)];
        p = g_bt2 + j;
    } else return;
    *p = __float2half_rn(v);
}

// ---------------- HMMA fp16 2-limb-A GEMM; C fp32 or fp16 ------------------
#define KC 64
#define STAGE 49152

__device__ __forceinline__ void load_chunk(
    unsigned st, const __half* __restrict__ Ah, const __half* __restrict__ Al,
    const __half* __restrict__ B, int m0, int k0, int M, int tid)
{
#pragma unroll
    for (int it = 0; it < 4; it++) {
        int idx = it * 256 + tid;
        int r = idx >> 3, c = idx & 7;
        unsigned d = st + (unsigned)((r << 7) + (((c ^ (r & 7)) & 7) << 4));
        int grow = m0 + r;
        int sz = (grow < M) ? 16 : 0;
        if (grow >= M) grow = M - 1;
        size_t go = (size_t)grow * 512 + k0 + c * 8;
        cp16(d,         Ah + go, sz);
        cp16(d + 16384, Al + go, sz);
        size_t gb = (size_t)r * 512 + k0 + c * 8;   // B pre-offset by nb rows
        cp16(d + 32768, B + gb, 16);
    }
}

template <bool CHALF>
__global__ __launch_bounds__(256) void gemm_tc(
    const __half* __restrict__ Ah, const __half* __restrict__ Al,
    const __half* __restrict__ Bg,
    void* __restrict__ Cv, int M, int ldc)
{
    extern __shared__ char smem[];
    const unsigned sbase = smem_u32(smem);
    const int tid = threadIdx.x, lane = tid & 31, wid = tid >> 5;
    const int m0 = blockIdx.y * 128;
    const int nb = blockIdx.x * 128;
    const __half* B = Bg + (size_t)nb * 512;
    const int wm = (wid & 3) * 32, wn = (wid >> 2) * 64;

    float acc[2][8][4];
#pragma unroll
    for (int i = 0; i < 2; i++)
#pragma unroll
        for (int j = 0; j < 8; j++)
#pragma unroll
            for (int q = 0; q < 4; q++) acc[i][j][q] = 0.f;

    load_chunk(sbase,         Ah, Al, B, m0, 0,  M, tid);
    cp_commit();
    load_chunk(sbase + STAGE, Ah, Al, B, m0, KC, M, tid);
    cp_commit();

    for (int kc = 0; kc < 8; kc++) {
        if (kc < 7)
            asm volatile("cp.async.wait_group 1;" ::: "memory");
        else
            asm volatile("cp.async.wait_group 0;" ::: "memory");
        __syncthreads();
        const unsigned st = sbase + (kc & 1) * STAGE;
#pragma unroll
        for (int kk = 0; kk < 4; kk++) {
            const int k = kk * 16;
            int ar = lane & 15;
            int ac = k + ((lane >> 4) << 3);
            unsigned ah[2][4], al[2][4];
            ldsm4(ah[0][0], ah[0][1], ah[0][2], ah[0][3], st + aoff(wm + ar, ac));
            ldsm4(ah[1][0], ah[1][1], ah[1][2], ah[1][3], st + aoff(wm + 16 + ar, ac));
            ldsm4(al[0][0], al[0][1], al[0][2], al[0][3], st + 16384 + aoff(wm + ar, ac));
            ldsm4(al[1][0], al[1][1], al[1][2], al[1][3], st + 16384 + aoff(wm + 16 + ar, ac));
            int br = (lane & 7) + ((lane >> 4) << 3);
            int bc = k + (((lane >> 3) & 1) << 3);
            unsigned b[8][2];
#pragma unroll
            for (int q = 0; q < 4; q++)
                ldsm4(b[2*q][0], b[2*q][1], b[2*q+1][0], b[2*q+1][1],
                      st + 32768 + aoff(wn + 16 * q + br, bc));
#pragma unroll
            for (int mt = 0; mt < 2; mt++)
#pragma unroll
                for (int nt = 0; nt < 8; nt++) {
                    mma16816(acc[mt][nt], ah[mt], b[nt]);
                    mma16816(acc[mt][nt], al[mt], b[nt]);
                }
        }
        __syncthreads();
        if (kc + 2 < 8) {
            load_chunk(sbase + (kc & 1) * STAGE, Ah, Al, B, m0, (kc + 2) * KC, M, tid);
            cp_commit();
        }
    }

#pragma unroll
    for (int mt = 0; mt < 2; mt++) {
        int r0 = m0 + wm + mt * 16 + (lane >> 2);
#pragma unroll
        for (int nt = 0; nt < 8; nt++) {
            int c0 = nb + wn + nt * 8 + (lane & 3) * 2;
            if (CHALF) {
                __half* C = (__half*)Cv;
                if (r0 < M)
                    *(__half2*)&C[(size_t)r0 * ldc + c0] =
                        __floats2half2_rn(acc[mt][nt][0], acc[mt][nt][1]);
                if (r0 + 8 < M)
                    *(__half2*)&C[(size_t)(r0 + 8) * ldc + c0] =
                        __floats2half2_rn(acc[mt][nt][2], acc[mt][nt][3]);
            } else {
                float* C = (float*)Cv;
                if (r0 < M)
                    *(float2*)&C[(size_t)r0 * ldc + c0] =
                        make_float2(acc[mt][nt][0], acc[mt][nt][1]);
                if (r0 + 8 < M)
                    *(float2*)&C[(size_t)(r0 + 8) * ldc + c0] =
                        make_float2(acc[mt][nt][2], acc[mt][nt][3]);
            }
        }
    }
}

// ---------------- layer-1 attention scalars (fp16 h) ----------------
__global__ __launch_bounds__(256) void scalars1_kernel(const float* __restrict__ As) {
    int n = blockIdx.x;
    int w = threadIdx.x >> 5, lane = threadIdx.x & 31;
    const __half2* hr = (const __half2*)(g_hh + (size_t)n * X2DIM + w * NHID);
    float2 f = __half22float2(hr[lane]);              // cols 2*lane, 2*lane+1
    const float* a = As + w * 2 * NHID;
    float d1 = f.x * a[2 * lane]      + f.y * a[2 * lane + 1];
    float d2 = f.x * a[64 + 2 * lane] + f.y * a[64 + 2 * lane + 1];
#pragma unroll
    for (int o = 16; o; o >>= 1) {
        d1 += __shfl_down_sync(0xffffffffu, d1, o);
        d2 += __shfl_down_sync(0xffffffffu, d2, o);
    }
    if (lane == 0) { g_s1[n * 8 + w] = d1; g_s2[n * 8 + w] = d2; }
}

// ---------------- layer-1 aggregation: warp-per-node, fp16 gather ----------
__global__ __launch_bounds__(256) void agg1_kernel(int N) {
    int n = (blockIdx.x * 256 + threadIdx.x) >> 5;
    if (n >= N) return;
    const int lane = threadIdx.x & 31;
    const int le = lane >> 3, hh = lane & 7;   // weight phase: edge-in-4, head
    const int hme = lane >> 2;                 // my head for gather/denominator
    const int beg = g_rowptr[n];
    const int deg = g_rowptr[n + 1] - beg;

    const float s1v = g_s1[n * 8 + hh];
    float acc[16];
#pragma unroll
    for (int i = 0; i < 16; i++) acc[i] = 0.f;
    float den = 0.f;

    for (int eb = 0; eb < deg; eb += 4) {
        const int cnt = min(4, deg - eb);
        int d_le = g_col[beg + ((le < cnt) ? (eb + le) : 0)];
        float logit = s1v + g_s2[d_le * 8 + hh];
        float lr = logit > 0.f ? logit : 0.2f * logit;
        float w_le = __expf(-lr);
#pragma unroll 4
        for (int e = 0; e < cnt; e++) {
            int   d = __shfl_sync(0xffffffffu, d_le, e << 3);
            float w = __shfl_sync(0xffffffffu, w_le, (e << 3) + hme);
            const uint4* hr = (const uint4*)(g_hh + (size_t)d * X2DIM) + lane * 2;
            uint4 pa = hr[0], pb = hr[1];
            const __half2* ha = (const __half2*)&pa;
            const __half2* hb = (const __half2*)&pb;
#pragma unroll
            for (int j = 0; j < 4; j++) {
                float2 fa = __half22float2(ha[j]);
                float2 fb = __half22float2(hb[j]);
                acc[2*j]     += w * fa.x; acc[2*j + 1] += w * fa.y;
                acc[8 + 2*j] += w * fb.x; acc[8 + 2*j + 1] += w * fb.y;
            }
            den += w;
        }
    }

    const float inv = 1.f / den;
    __half hi[16], lo[16];
#pragma unroll
    for (int i = 0; i < 16; i++) {
        float t = acc[i] * inv;
        t = t > 0.f ? t : expm1f(t);
        __half h = __float2half_rn(t);
        hi[i] = h;
        lo[i] = __float2half_rn(t - __half2float(h));
    }
    size_t o = (size_t)n * X2DIM + lane * 16;
    ((uint4*)(g_x2h + o))[0] = *(uint4*)(hi);
    ((uint4*)(g_x2h + o))[1] = *(uint4*)(hi + 8);
    ((uint4*)(g_x2l + o))[0] = *(uint4*)(lo);
    ((uint4*)(g_x2l + o))[1] = *(uint4*)(lo + 8);
}

// ---------------- layer-2 attention scalars ----------------
__global__ __launch_bounds__(128) void scalars2_kernel(
    const float* __restrict__ mua, const float* __restrict__ lva)
{
    int n = blockIdx.x, t = threadIdx.x;
    float hmu = g_hml[(size_t)n * 256 + t];
    float hlv = g_hml[(size_t)n * 256 + 128 + t];
    float p0 = hmu * mua[t];
    float p1 = hmu * mua[128 + t];
    float p2 = hlv * lva[t];
    float p3 = hlv * lva[128 + t];
#pragma unroll
    for (int o = 16; o; o >>= 1) {
        p0 += __shfl_down_sync(0xffffffffu, p0, o);
        p1 += __shfl_down_sync(0xffffffffu, p1, o);
        p2 += __shfl_down_sync(0xffffffffu, p2, o);
        p3 += __shfl_down_sync(0xffffffffu, p3, o);
    }
    __shared__ float red[4][4];
    int w = t >> 5, lane = t & 31;
    if (lane == 0) { red[w][0] = p0; red[w][1] = p1; red[w][2] = p2; red[w][3] = p3; }
    __syncthreads();
    if (t == 0) {
        g_smu1[n] = red[0][0] + red[1][0] + red[2][0] + red[3][0];
        g_smu2[n] = red[0][1] + red[1][1] + red[2][1] + red[3][1];
        g_slv1[n] = red[0][2] + red[1][2] + red[2][2] + red[3][2];
        g_slv2[n] = red[0][3] + red[1][3] + red[2][3] + red[3][3];
    }
}

// ---------------- layer-2 aggregation: warp-per-node + reparameterize ------
__device__ __forceinline__ void fma4(float4& a, float w, const float4& v) {
    a.x += w * v.x; a.y += w * v.y; a.z += w * v.z; a.w += w * v.w;
}

__global__ __launch_bounds__(256) void agg2_kernel(
    const float* __restrict__ eps, float* __restrict__ out, int N)
{
    int n = (blockIdx.x * 256 + threadIdx.x) >> 5;
    if (n >= N) return;
    const int lane = threadIdx.x & 31;
    const int beg = g_rowptr[n];
    const int deg = g_rowptr[n + 1] - beg;
    const float bmu = g_smu1[n], blv = g_slv1[n];

    float4 amu = make_float4(0,0,0,0), alv = amu;
    float dmu = 0.f, dlv = 0.f;

    for (int eb = 0; eb < deg; eb += 32) {
        const int cnt = min(32, deg - eb);
        int d_l = g_col[beg + ((lane < cnt) ? (eb + lane) : 0)];
        float lmu = bmu + g_smu2[d_l];
        float llv = blv + g_slv2[d_l];
        lmu = lmu > 0.f ? lmu : 0.2f * lmu;
        llv = llv > 0.f ? llv : 0.2f * llv;
        float wmu_l = __expf(-lmu);
        float wlv_l = __expf(-llv);
#pragma unroll 4
        for (int e = 0; e < cnt; e++) {
            int   d   = __shfl_sync(0xffffffffu, d_l,   e);
            float wmu = __shfl_sync(0xffffffffu, wmu_l, e);
            float wlv = __shfl_sync(0xffffffffu, wlv_l, e);
            const float4* pm = (const float4*)(g_hml + (size_t)d * 256) + lane;
            fma4(amu, wmu, pm[0]);
            fma4(alv, wlv, pm[32]);
            dmu += wmu; dlv += wlv;
        }
    }

    const float imu = 1.f / dmu, ilv = 1.f / dlv;
    float4 mu = make_float4(amu.x*imu, amu.y*imu, amu.z*imu, amu.w*imu);
    float4 lv = make_float4(alv.x*ilv, alv.y*ilv, alv.z*ilv, alv.w*ilv);
    float4 ev = *(const float4*)(eps + (size_t)n * NOUT + lane * 4);
    float4 z  = make_float4(ev.x * expf(lv.x) + mu.x,
                            ev.y * expf(lv.y) + mu.y,
                            ev.z * expf(lv.z) + mu.z,
                            ev.w * expf(lv.w) + mu.w);
    size_t NO = (size_t)N * NOUT;
    size_t o  = (size_t)n * NOUT + lane * 4;
    *(float4*)(out + o)          = z;
    *(float4*)(out + NO + o)     = mu;
    *(float4*)(out + 2 * NO + o) = lv;
}

// ---------------- host orchestration ----------------
extern "C" void kernel_launch(void* const* d_in, const int* in_sizes, int n_in,
                              void* d_out, int out_size)
{
    const float* x   = (const float*)d_in[0];
    const float* Ws  = (const float*)d_in[1];
    const float* As  = (const float*)d_in[2];
    const float* muW = (const float*)d_in[3];
    const float* mua = (const float*)d_in[4];
    const float* lvW = (const float*)d_in[5];
    const float* lva = (const float*)d_in[6];
    const float* eps = (const float*)d_in[7];
    const int*   ei  = (const int*)d_in[8];
    int E = in_sizes[8] / 2;
    int N = in_sizes[0] / NFEAT;
    float* out = (float*)d_out;

    float* p_hml;
    __half *p_hh, *p_xh, *p_xl, *p_x2h, *p_x2l, *p_bt1, *p_bt2;
    cudaGetSymbolAddress((void**)&p_hh,   g_hh);
    cudaGetSymbolAddress((void**)&p_hml,  g_hml);
    cudaGetSymbolAddress((void**)&p_xh,   g_xh);
    cudaGetSymbolAddress((void**)&p_xl,   g_xl);
    cudaGetSymbolAddress((void**)&p_x2h,  g_x2h);
    cudaGetSymbolAddress((void**)&p_x2l,  g_x2l);
    cudaGetSymbolAddress((void**)&p_bt1,  g_bt1);
    cudaGetSymbolAddress((void**)&p_bt2,  g_bt2);

    cudaFuncSetAttribute(gemm_tc<true>, cudaFuncAttributeMaxDynamicSharedMemorySize,
                         2 * STAGE);
    cudaFuncSetAttribute(gemm_tc<false>, cudaFuncAttributeMaxDynamicSharedMemorySize,
                         2 * STAGE);

    int mtiles = (N + 127) / 128;
    int wblocks = (N + 7) / 8;     // warp-per-node kernels: 8 warps/block

    // gemm_tc (layer-1) kept at the ncu-profiled launch slot (#3)
    convert_x_kernel<<<(N * NFEAT / 4 + 255) / 256, 256>>>(x, N * NFEAT / 4);     // 0
    convert_w_kernel<<<(512 * 512 + 256 * 512 + 255) / 256, 256>>>(Ws, muW, lvW); // 1
    zero_kernel<<<(N + 255) / 256, 256>>>(N);                                     // 2
    gemm_tc<true><<<dim3(4, mtiles), 256, 2 * STAGE>>>(p_xh, p_xl, p_bt1,         // 3
                                                       p_hh, N, X2DIM);
    hist_kernel<<<(E + 255) / 256, 256>>>(ei, E);                                 // 4
    scan_kernel<<<1, 1024>>>(N);                                                  // 5
    fill_kernel<<<(E + 255) / 256, 256>>>(ei, E);                                 // 6
    scalars1_kernel<<<N, 256>>>(As);                                              // 7
    agg1_kernel<<<wblocks, 256>>>(N);                                             // 8
    gemm_tc<false><<<dim3(2, mtiles), 256, 2 * STAGE>>>(p_x2h, p_x2l, p_bt2,      // 9
                                                        p_hml, N, 256);
    scalars2_kernel<<<N, 128>>>(mua, lva);                                        // 10
    agg2_kernel<<<wblocks, 256>>>(eps, out, N);                                   // 11
}

// round 10
// speedup vs baseline: 1.4482x; 1.0049x over previous
#include <cuda_runtime.h>
#include <cuda_fp16.h>
#include <cstdint>

// ---------------- problem constants ----------------
#define N_NODES  50000
#define E_MAX    450000
#define NFEAT    512
#define NHID     64
#define NHEADS   8
#define NOUT     128
#define X2DIM    512

// ---------------- device scratch ----------------
__device__ __half g_hh [(size_t)N_NODES * X2DIM];   // layer-1 head features, fp16
__device__ __half g_hml[(size_t)N_NODES * 256];     // fp16: [:,0:128]=h_mu, [:,128:256]=h_lv
__device__ float g_s1  [N_NODES * NHEADS];
__device__ float g_s2  [N_NODES * NHEADS];
__device__ float g_smu1[N_NODES], g_smu2[N_NODES], g_slv1[N_NODES], g_slv2[N_NODES];
__device__ int   g_rowptr[N_NODES + 1];
__device__ int   g_col [E_MAX];
__device__ int   g_cnt [N_NODES];
__device__ int   g_cursor[N_NODES];

// fp16 2-limb activations, fp16 1-limb weights
__device__ __half g_xh [(size_t)N_NODES * NFEAT];
__device__ __half g_xl [(size_t)N_NODES * NFEAT];
__device__ __half g_x2h[(size_t)N_NODES * X2DIM];
__device__ __half g_x2l[(size_t)N_NODES * X2DIM];
__device__ __half g_bt1[512 * 512];                 // Ws^T        [512,512]
__device__ __half g_bt2[256 * 512];                 // [muW;lvW]^T [256,512]

// ---------------- PTX helpers (target-generic, sm_80+) ----------------
__device__ __forceinline__ unsigned smem_u32(const void* p) {
    unsigned r;
    asm("{ .reg .u64 t; cvta.to.shared.u64 t, %1; cvt.u32.u64 %0, t; }"
        : "=r"(r) : "l"(p));
    return r;
}
__device__ __forceinline__ void cp16(unsigned dst, const void* src, int srcsz) {
    asm volatile("cp.async.cg.shared.global [%0], [%1], 16, %2;"
                 :: "r"(dst), "l"(src), "r"(srcsz) : "memory");
}
__device__ __forceinline__ void cp_commit() {
    asm volatile("cp.async.commit_group;" ::: "memory");
}
__device__ __forceinline__ void ldsm4(unsigned& r0, unsigned& r1, unsigned& r2,
                                      unsigned& r3, unsigned a) {
    asm volatile("ldmatrix.sync.aligned.m8n8.x4.shared.b16 {%0,%1,%2,%3}, [%4];"
                 : "=r"(r0), "=r"(r1), "=r"(r2), "=r"(r3) : "r"(a));
}
__device__ __forceinline__ void mma16816(float* d, const unsigned* a, const unsigned* b) {
    asm volatile(
        "mma.sync.aligned.m16n8k16.row.col.f32.f16.f16.f32 "
        "{%0,%1,%2,%3}, {%4,%5,%6,%7}, {%8,%9}, {%0,%1,%2,%3};"
        : "+f"(d[0]), "+f"(d[1]), "+f"(d[2]), "+f"(d[3])
        : "r"(a[0]), "r"(a[1]), "r"(a[2]), "r"(a[3]), "r"(b[0]), "r"(b[1]));
}
// swizzled byte offset inside a tile whose rows are 64 fp16 = 128B
__device__ __forceinline__ unsigned aoff(int r, int k) {
    return (unsigned)((r << 7) + (((((k >> 3) ^ r) & 7)) << 4) + ((k & 7) << 1));
}

// ---------------- CSR construction ----------------
__global__ void zero_kernel(int n) {
    int i = blockIdx.x * blockDim.x + threadIdx.x;
    if (i < n) { g_cnt[i] = 0; g_cursor[i] = 0; }
}
__global__ void hist_kernel(const int* __restrict__ ei, int E) {
    int e = blockIdx.x * blockDim.x + threadIdx.x;
    if (e < E) atomicAdd(&g_cnt[ei[e]], 1);
}
__global__ void scan_kernel(int n) {
    __shared__ int sh[1024];
    __shared__ int carry;
    if (threadIdx.x == 0) carry = 0;
    __syncthreads();
    for (int base = 0; base < n; base += 1024) {
        int i = base + threadIdx.x;
        int v = (i < n) ? g_cnt[i] : 0;
        sh[threadIdx.x] = v;
        __syncthreads();
        for (int off = 1; off < 1024; off <<= 1) {
            int t = (threadIdx.x >= off) ? sh[threadIdx.x - off] : 0;
            __syncthreads();
            sh[threadIdx.x] += t;
            __syncthreads();
        }
        if (i < n) g_rowptr[i] = carry + sh[threadIdx.x] - v;
        __syncthreads();
        if (threadIdx.x == 0) carry += sh[1023];
        __syncthreads();
    }
    if (threadIdx.x == 0) g_rowptr[n] = carry;
}
__global__ void fill_kernel(const int* __restrict__ ei, int E) {
    int e = blockIdx.x * blockDim.x + threadIdx.x;
    if (e < E) {
        int s = ei[e];
        int d = ei[E + e];
        int p = atomicAdd(&g_cursor[s], 1);
        g_col[g_rowptr[s] + p] = d;
    }
}

// ---------------- conversions ----------------
__global__ void convert_x_kernel(const float* __restrict__ x, int n4) {
    int i = blockIdx.x * blockDim.x + threadIdx.x;
    if (i >= n4) return;
    float4 v = ((const float4*)x)[i];
    __half h0 = __float2half_rn(v.x);
    __half h1 = __float2half_rn(v.y);
    __half h2 = __float2half_rn(v.z);
    __half h3 = __float2half_rn(v.w);
    __half l0 = __float2half_rn(v.x - __half2float(h0));
    __half l1 = __float2half_rn(v.y - __half2float(h1));
    __half l2 = __float2half_rn(v.z - __half2float(h2));
    __half l3 = __float2half_rn(v.w - __half2float(h3));
    ((__half2*)g_xh)[i * 2]     = __half2(h0, h1);
    ((__half2*)g_xh)[i * 2 + 1] = __half2(h2, h3);
    ((__half2*)g_xl)[i * 2]     = __half2(l0, l1);
    ((__half2*)g_xl)[i * 2 + 1] = __half2(l2, l3);
}

__global__ void convert_w_kernel(const float* __restrict__ Ws,
                                 const float* __restrict__ muW,
                                 const float* __restrict__ lvW) {
    int i = blockIdx.x * blockDim.x + threadIdx.x;
    float v;
    __half* p;
    if (i < 512 * 512) {
        int row = i >> 9, k = i & 511;            // row = h*64 + n
        int h = row >> 6, n = row & 63;
        v = Ws[((size_t)h * 512 + k) * 64 + n];
        p = g_bt1 + i;
    } else if (i < 512 * 512 + 256 * 512) {
        int j = i - 512 * 512;
        int n = j >> 9, k = j & 511;
        v = (n < 128) ? muW[(size_t)k * 128 + n]
                      : lvW[(size_t)k * 128 + (n - 128)];
        p = g_bt2 + j;
    } else return;
    *p = __float2half_rn(v);
}

// ---------------- HMMA fp16 2-limb-A GEMM; C fp16 --------------------------
#define KC 64
#define STAGE 49152

__device__ __forceinline__ void load_chunk(
    unsigned st, const __half* __restrict__ Ah, const __half* __restrict__ Al,
    const __half* __restrict__ B, int m0, int k0, int M, int tid)
{
#pragma unroll
    for (int it = 0; it < 4; it++) {
        int idx = it * 256 + tid;
        int r = idx >> 3, c = idx & 7;
        unsigned d = st + (unsigned)((r << 7) + (((c ^ (r & 7)) & 7) << 4));
        int grow = m0 + r;
        int sz = (grow < M) ? 16 : 0;
        if (grow >= M) grow = M - 1;
        size_t go = (size_t)grow * 512 + k0 + c * 8;
        cp16(d,         Ah + go, sz);
        cp16(d + 16384, Al + go, sz);
        size_t gb = (size_t)r * 512 + k0 + c * 8;   // B pre-offset by nb rows
        cp16(d + 32768, B + gb, 16);
    }
}

__global__ __launch_bounds__(256) void gemm_tc(
    const __half* __restrict__ Ah, const __half* __restrict__ Al,
    const __half* __restrict__ Bg,
    __half* __restrict__ C, int M, int ldc)
{
    extern __shared__ char smem[];
    const unsigned sbase = smem_u32(smem);
    const int tid = threadIdx.x, lane = tid & 31, wid = tid >> 5;
    const int m0 = blockIdx.y * 128;
    const int nb = blockIdx.x * 128;
    const __half* B = Bg + (size_t)nb * 512;
    const int wm = (wid & 3) * 32, wn = (wid >> 2) * 64;

    float acc[2][8][4];
#pragma unroll
    for (int i = 0; i < 2; i++)
#pragma unroll
        for (int j = 0; j < 8; j++)
#pragma unroll
            for (int q = 0; q < 4; q++) acc[i][j][q] = 0.f;

    load_chunk(sbase,         Ah, Al, B, m0, 0,  M, tid);
    cp_commit();
    load_chunk(sbase + STAGE, Ah, Al, B, m0, KC, M, tid);
    cp_commit();

    for (int kc = 0; kc < 8; kc++) {
        if (kc < 7)
            asm volatile("cp.async.wait_group 1;" ::: "memory");
        else
            asm volatile("cp.async.wait_group 0;" ::: "memory");
        __syncthreads();
        const unsigned st = sbase + (kc & 1) * STAGE;
#pragma unroll
        for (int kk = 0; kk < 4; kk++) {
            const int k = kk * 16;
            int ar = lane & 15;
            int ac = k + ((lane >> 4) << 3);
            unsigned ah[2][4], al[2][4];
            ldsm4(ah[0][0], ah[0][1], ah[0][2], ah[0][3], st + aoff(wm + ar, ac));
            ldsm4(ah[1][0], ah[1][1], ah[1][2], ah[1][3], st + aoff(wm + 16 + ar, ac));
            ldsm4(al[0][0], al[0][1], al[0][2], al[0][3], st + 16384 + aoff(wm + ar, ac));
            ldsm4(al[1][0], al[1][1], al[1][2], al[1][3], st + 16384 + aoff(wm + 16 + ar, ac));
            int br = (lane & 7) + ((lane >> 4) << 3);
            int bc = k + (((lane >> 3) & 1) << 3);
            unsigned b[8][2];
#pragma unroll
            for (int q = 0; q < 4; q++)
                ldsm4(b[2*q][0], b[2*q][1], b[2*q+1][0], b[2*q+1][1],
                      st + 32768 + aoff(wn + 16 * q + br, bc));
#pragma unroll
            for (int mt = 0; mt < 2; mt++)
#pragma unroll
                for (int nt = 0; nt < 8; nt++) {
                    mma16816(acc[mt][nt], ah[mt], b[nt]);
                    mma16816(acc[mt][nt], al[mt], b[nt]);
                }
        }
        __syncthreads();
        if (kc + 2 < 8) {
            load_chunk(sbase + (kc & 1) * STAGE, Ah, Al, B, m0, (kc + 2) * KC, M, tid);
            cp_commit();
        }
    }

#pragma unroll
    for (int mt = 0; mt < 2; mt++) {
        int r0 = m0 + wm + mt * 16 + (lane >> 2);
#pragma unroll
        for (int nt = 0; nt < 8; nt++) {
            int c0 = nb + wn + nt * 8 + (lane & 3) * 2;
            if (r0 < M)
                *(__half2*)&C[(size_t)r0 * ldc + c0] =
                    __floats2half2_rn(acc[mt][nt][0], acc[mt][nt][1]);
            if (r0 + 8 < M)
                *(__half2*)&C[(size_t)(r0 + 8) * ldc + c0] =
                    __floats2half2_rn(acc[mt][nt][2], acc[mt][nt][3]);
        }
    }
}

// ---------------- layer-1 attention scalars (fp16 h) ----------------
__global__ __launch_bounds__(256) void scalars1_kernel(const float* __restrict__ As) {
    int n = blockIdx.x;
    int w = threadIdx.x >> 5, lane = threadIdx.x & 31;
    const __half2* hr = (const __half2*)(g_hh + (size_t)n * X2DIM + w * NHID);
    float2 f = __half22float2(hr[lane]);              // cols 2*lane, 2*lane+1
    const float* a = As + w * 2 * NHID;
    float d1 = f.x * a[2 * lane]      + f.y * a[2 * lane + 1];
    float d2 = f.x * a[64 + 2 * lane] + f.y * a[64 + 2 * lane + 1];
#pragma unroll
    for (int o = 16; o; o >>= 1) {
        d1 += __shfl_down_sync(0xffffffffu, d1, o);
        d2 += __shfl_down_sync(0xffffffffu, d2, o);
    }
    if (lane == 0) { g_s1[n * 8 + w] = d1; g_s2[n * 8 + w] = d2; }
}

// ---------------- layer-1 aggregation: warp-per-node, fp16 gather ----------
__global__ __launch_bounds__(256) void agg1_kernel(int N) {
    int n = (blockIdx.x * 256 + threadIdx.x) >> 5;
    if (n >= N) return;
    const int lane = threadIdx.x & 31;
    const int le = lane >> 3, hh = lane & 7;   // weight phase: edge-in-4, head
    const int hme = lane >> 2;                 // my head for gather/denominator
    const int beg = g_rowptr[n];
    const int deg = g_rowptr[n + 1] - beg;

    const float s1v = g_s1[n * 8 + hh];
    float acc[16];
#pragma unroll
    for (int i = 0; i < 16; i++) acc[i] = 0.f;
    float den = 0.f;

    for (int eb = 0; eb < deg; eb += 4) {
        const int cnt = min(4, deg - eb);
        int d_le = g_col[beg + ((le < cnt) ? (eb + le) : 0)];
        float logit = s1v + g_s2[d_le * 8 + hh];
        float lr = logit > 0.f ? logit : 0.2f * logit;
        float w_le = __expf(-lr);
#pragma unroll 4
        for (int e = 0; e < cnt; e++) {
            int   d = __shfl_sync(0xffffffffu, d_le, e << 3);
            float w = __shfl_sync(0xffffffffu, w_le, (e << 3) + hme);
            const uint4* hr = (const uint4*)(g_hh + (size_t)d * X2DIM) + lane * 2;
            uint4 pa = hr[0], pb = hr[1];
            const __half2* ha = (const __half2*)&pa;
            const __half2* hb = (const __half2*)&pb;
#pragma unroll
            for (int j = 0; j < 4; j++) {
                float2 fa = __half22float2(ha[j]);
                float2 fb = __half22float2(hb[j]);
                acc[2*j]     += w * fa.x; acc[2*j + 1] += w * fa.y;
                acc[8 + 2*j] += w * fb.x; acc[8 + 2*j + 1] += w * fb.y;
            }
            den += w;
        }
    }

    const float inv = 1.f / den;
    __half hi[16], lo[16];
#pragma unroll
    for (int i = 0; i < 16; i++) {
        float t = acc[i] * inv;
        t = t > 0.f ? t : expm1f(t);
        __half h = __float2half_rn(t);
        hi[i] = h;
        lo[i] = __float2half_rn(t - __half2float(h));
    }
    size_t o = (size_t)n * X2DIM + lane * 16;
    ((uint4*)(g_x2h + o))[0] = *(uint4*)(hi);
    ((uint4*)(g_x2h + o))[1] = *(uint4*)(hi + 8);
    ((uint4*)(g_x2l + o))[0] = *(uint4*)(lo);
    ((uint4*)(g_x2l + o))[1] = *(uint4*)(lo + 8);
}

// ---------------- layer-2 attention scalars (fp16 hml) ----------------
__global__ __launch_bounds__(128) void scalars2_kernel(
    const float* __restrict__ mua, const float* __restrict__ lva)
{
    int n = blockIdx.x, t = threadIdx.x;
    float hmu = __half2float(g_hml[(size_t)n * 256 + t]);
    float hlv = __half2float(g_hml[(size_t)n * 256 + 128 + t]);
    float p0 = hmu * mua[t];
    float p1 = hmu * mua[128 + t];
    float p2 = hlv * lva[t];
    float p3 = hlv * lva[128 + t];
#pragma unroll
    for (int o = 16; o; o >>= 1) {
        p0 += __shfl_down_sync(0xffffffffu, p0, o);
        p1 += __shfl_down_sync(0xffffffffu, p1, o);
        p2 += __shfl_down_sync(0xffffffffu, p2, o);
        p3 += __shfl_down_sync(0xffffffffu, p3, o);
    }
    __shared__ float red[4][4];
    int w = t >> 5, lane = t & 31;
    if (lane == 0) { red[w][0] = p0; red[w][1] = p1; red[w][2] = p2; red[w][3] = p3; }
    __syncthreads();
    if (t == 0) {
        g_smu1[n] = red[0][0] + red[1][0] + red[2][0] + red[3][0];
        g_smu2[n] = red[0][1] + red[1][1] + red[2][1] + red[3][1];
        g_slv1[n] = red[0][2] + red[1][2] + red[2][2] + red[3][2];
        g_slv2[n] = red[0][3] + red[1][3] + red[2][3] + red[3][3];
    }
}

// ---------------- layer-2 aggregation: warp-per-node, fp16 gather ----------
__global__ __launch_bounds__(256) void agg2_kernel(
    const float* __restrict__ eps, float* __restrict__ out, int N)
{
    int n = (blockIdx.x * 256 + threadIdx.x) >> 5;
    if (n >= N) return;
    const int lane = threadIdx.x & 31;
    const int beg = g_rowptr[n];
    const int deg = g_rowptr[n + 1] - beg;
    const float bmu = g_smu1[n], blv = g_slv1[n];

    float amu[4] = {0,0,0,0}, alv[4] = {0,0,0,0};
    float dmu = 0.f, dlv = 0.f;

    for (int eb = 0; eb < deg; eb += 32) {
        const int cnt = min(32, deg - eb);
        int d_l = g_col[beg + ((lane < cnt) ? (eb + lane) : 0)];
        float lmu = bmu + g_smu2[d_l];
        float llv = blv + g_slv2[d_l];
        lmu = lmu > 0.f ? lmu : 0.2f * lmu;
        llv = llv > 0.f ? llv : 0.2f * llv;
        float wmu_l = __expf(-lmu);
        float wlv_l = __expf(-llv);
#pragma unroll 4
        for (int e = 0; e < cnt; e++) {
            int   d   = __shfl_sync(0xffffffffu, d_l,   e);
            float wmu = __shfl_sync(0xffffffffu, wmu_l, e);
            float wlv = __shfl_sync(0xffffffffu, wlv_l, e);
            const __half* base = g_hml + (size_t)d * 256;
            uint2 pm = *(const uint2*)(base + lane * 4);
            uint2 pl = *(const uint2*)(base + 128 + lane * 4);
            const __half2* hm = (const __half2*)&pm;
            const __half2* hl = (const __half2*)&pl;
            float2 m0 = __half22float2(hm[0]), m1 = __half22float2(hm[1]);
            float2 l0 = __half22float2(hl[0]), l1 = __half22float2(hl[1]);
            amu[0] += wmu * m0.x; amu[1] += wmu * m0.y;
            amu[2] += wmu * m1.x; amu[3] += wmu * m1.y;
            alv[0] += wlv * l0.x; alv[1] += wlv * l0.y;
            alv[2] += wlv * l1.x; alv[3] += wlv * l1.y;
            dmu += wmu; dlv += wlv;
        }
    }

    const float imu = 1.f / dmu, ilv = 1.f / dlv;
    float4 mu = make_float4(amu[0]*imu, amu[1]*imu, amu[2]*imu, amu[3]*imu);
    float4 lv = make_float4(alv[0]*ilv, alv[1]*ilv, alv[2]*ilv, alv[3]*ilv);
    float4 ev = *(const float4*)(eps + (size_t)n * NOUT + lane * 4);
    float4 z  = make_float4(ev.x * expf(lv.x) + mu.x,
                            ev.y * expf(lv.y) + mu.y,
                            ev.z * expf(lv.z) + mu.z,
                            ev.w * expf(lv.w) + mu.w);
    size_t NO = (size_t)N * NOUT;
    size_t o  = (size_t)n * NOUT + lane * 4;
    *(float4*)(out + o)          = z;
    *(float4*)(out + NO + o)     = mu;
    *(float4*)(out + 2 * NO + o) = lv;
}

// ---------------- host orchestration ----------------
extern "C" void kernel_launch(void* const* d_in, const int* in_sizes, int n_in,
                              void* d_out, int out_size)
{
    const float* x   = (const float*)d_in[0];
    const float* Ws  = (const float*)d_in[1];
    const float* As  = (const float*)d_in[2];
    const float* muW = (const float*)d_in[3];
    const float* mua = (const float*)d_in[4];
    const float* lvW = (const float*)d_in[5];
    const float* lva = (const float*)d_in[6];
    const float* eps = (const float*)d_in[7];
    const int*   ei  = (const int*)d_in[8];
    int E = in_sizes[8] / 2;
    int N = in_sizes[0] / NFEAT;
    float* out = (float*)d_out;

    __half *p_hh, *p_hml, *p_xh, *p_xl, *p_x2h, *p_x2l, *p_bt1, *p_bt2;
    cudaGetSymbolAddress((void**)&p_hh,   g_hh);
    cudaGetSymbolAddress((void**)&p_hml,  g_hml);
    cudaGetSymbolAddress((void**)&p_xh,   g_xh);
    cudaGetSymbolAddress((void**)&p_xl,   g_xl);
    cudaGetSymbolAddress((void**)&p_x2h,  g_x2h);
    cudaGetSymbolAddress((void**)&p_x2l,  g_x2l);
    cudaGetSymbolAddress((void**)&p_bt1,  g_bt1);
    cudaGetSymbolAddress((void**)&p_bt2,  g_bt2);

    cudaFuncSetAttribute(gemm_tc, cudaFuncAttributeMaxDynamicSharedMemorySize,
                         2 * STAGE);

    int mtiles = (N + 127) / 128;
    int wblocks = (N + 7) / 8;     // warp-per-node kernels: 8 warps/block

    // gemm_tc (layer-1) kept at the ncu-profiled launch slot (#3)
    convert_x_kernel<<<(N * NFEAT / 4 + 255) / 256, 256>>>(x, N * NFEAT / 4);     // 0
    convert_w_kernel<<<(512 * 512 + 256 * 512 + 255) / 256, 256>>>(Ws, muW, lvW); // 1
    zero_kernel<<<(N + 255) / 256, 256>>>(N);                                     // 2
    gemm_tc<<<dim3(4, mtiles), 256, 2 * STAGE>>>(p_xh, p_xl, p_bt1,               // 3
                                                 p_hh, N, X2DIM);
    hist_kernel<<<(E + 255) / 256, 256>>>(ei, E);                                 // 4
    scan_kernel<<<1, 1024>>>(N);                                                  // 5
    fill_kernel<<<(E + 255) / 256, 256>>>(ei, E);                                 // 6
    scalars1_kernel<<<N, 256>>>(As);                                              // 7
    agg1_kernel<<<wblocks, 256>>>(N);                                             // 8
    gemm_tc<<<dim3(2, mtiles), 256, 2 * STAGE>>>(p_x2h, p_x2l, p_bt2,             // 9
                                                 p_hml, N, 256);
    scalars2_kernel<<<N, 128>>>(mua, lva);                                        // 10
    agg2_kernel<<<wblocks, 256>>>(eps, out, N);                                   // 11
}

// round 11
// speedup vs baseline: 1.8502x; 1.2776x over previous
#include <cuda_runtime.h>
#include <cuda_fp16.h>
#include <cstdint>

// ---------------- problem constants ----------------
#define N_NODES  50000
#define E_MAX    450000
#define NFEAT    512
#define NHID     64
#define NHEADS   8
#define NOUT     128
#define X2DIM    512

// ---------------- device scratch ----------------
__device__ __half g_hh [(size_t)N_NODES * X2DIM];   // layer-1 head features, fp16
__device__ __half g_hml[(size_t)N_NODES * 256];     // fp16: [:,0:128]=h_mu, [:,128:256]=h_lv
__device__ float g_s1  [N_NODES * NHEADS];
__device__ float g_s2  [N_NODES * NHEADS];
__device__ float g_smu1[N_NODES], g_smu2[N_NODES], g_slv1[N_NODES], g_slv2[N_NODES];
__device__ int   g_rowptr[N_NODES + 1];
__device__ int   g_col [E_MAX];
__device__ int   g_cnt [N_NODES];
__device__ int   g_cursor[N_NODES];

// fp16 activations (single limb), fp16 weights
__device__ __half g_xh [(size_t)N_NODES * NFEAT];
__device__ __half g_x2h[(size_t)N_NODES * X2DIM];
__device__ __half g_bt1[512 * 512];                 // Ws^T        [512,512]
__device__ __half g_bt2[256 * 512];                 // [muW;lvW]^T [256,512]

// ---------------- PTX helpers (target-generic, sm_80+) ----------------
__device__ __forceinline__ unsigned smem_u32(const void* p) {
    unsigned r;
    asm("{ .reg .u64 t; cvta.to.shared.u64 t, %1; cvt.u32.u64 %0, t; }"
        : "=r"(r) : "l"(p));
    return r;
}
__device__ __forceinline__ void cp16(unsigned dst, const void* src, int srcsz) {
    asm volatile("cp.async.cg.shared.global [%0], [%1], 16, %2;"
                 :: "r"(dst), "l"(src), "r"(srcsz) : "memory");
}
__device__ __forceinline__ void cp_commit() {
    asm volatile("cp.async.commit_group;" ::: "memory");
}
__device__ __forceinline__ void ldsm4(unsigned& r0, unsigned& r1, unsigned& r2,
                                      unsigned& r3, unsigned a) {
    asm volatile("ldmatrix.sync.aligned.m8n8.x4.shared.b16 {%0,%1,%2,%3}, [%4];"
                 : "=r"(r0), "=r"(r1), "=r"(r2), "=r"(r3) : "r"(a));
}
__device__ __forceinline__ void mma16816(float* d, const unsigned* a, const unsigned* b) {
    asm volatile(
        "mma.sync.aligned.m16n8k16.row.col.f32.f16.f16.f32 "
        "{%0,%1,%2,%3}, {%4,%5,%6,%7}, {%8,%9}, {%0,%1,%2,%3};"
        : "+f"(d[0]), "+f"(d[1]), "+f"(d[2]), "+f"(d[3])
        : "r"(a[0]), "r"(a[1]), "r"(a[2]), "r"(a[3]), "r"(b[0]), "r"(b[1]));
}
// swizzled byte offset inside a tile whose rows are 64 fp16 = 128B
__device__ __forceinline__ unsigned aoff(int r, int k) {
    return (unsigned)((r << 7) + (((((k >> 3) ^ r) & 7)) << 4) + ((k & 7) << 1));
}

// ---------------- CSR construction ----------------
__global__ void zero_kernel(int n) {
    int i = blockIdx.x * blockDim.x + threadIdx.x;
    if (i < n) { g_cnt[i] = 0; g_cursor[i] = 0; }
}
__global__ void hist_kernel(const int* __restrict__ ei, int E) {
    int e = blockIdx.x * blockDim.x + threadIdx.x;
    if (e < E) atomicAdd(&g_cnt[ei[e]], 1);
}
// one-pass scan: 1024 threads, each owns a contiguous chunk
__global__ __launch_bounds__(1024) void scan_kernel(int n) {
    __shared__ int sh[1024];
    const int t = threadIdx.x;
    const int per = (n + 1023) / 1024;
    const int lo = min(t * per, n), hi = min(lo + per, n);
    int sum = 0;
    for (int i = lo; i < hi; i++) sum += g_cnt[i];
    sh[t] = sum;
    __syncthreads();
    // Hillis-Steele inclusive scan over 1024 thread sums
    for (int off = 1; off < 1024; off <<= 1) {
        int v = (t >= off) ? sh[t - off] : 0;
        __syncthreads();
        sh[t] += v;
        __syncthreads();
    }
    int run = sh[t] - sum;          // exclusive offset for this chunk
    for (int i = lo; i < hi; i++) {
        g_rowptr[i] = run;
        run += g_cnt[i];
    }
    if (t == 1023) g_rowptr[n] = sh[1023];
}
__global__ void fill_kernel(const int* __restrict__ ei, int E) {
    int e = blockIdx.x * blockDim.x + threadIdx.x;
    if (e < E) {
        int s = ei[e];
        int d = ei[E + e];
        int p = atomicAdd(&g_cursor[s], 1);
        g_col[g_rowptr[s] + p] = d;
    }
}

// ---------------- conversions ----------------
__global__ void convert_x_kernel(const float* __restrict__ x, int n4) {
    int i = blockIdx.x * blockDim.x + threadIdx.x;
    if (i >= n4) return;
    float4 v = ((const float4*)x)[i];
    ((__half2*)g_xh)[i * 2]     = __floats2half2_rn(v.x, v.y);
    ((__half2*)g_xh)[i * 2 + 1] = __floats2half2_rn(v.z, v.w);
}

__global__ void convert_w_kernel(const float* __restrict__ Ws,
                                 const float* __restrict__ muW,
                                 const float* __restrict__ lvW) {
    int i = blockIdx.x * blockDim.x + threadIdx.x;
    float v;
    __half* p;
    if (i < 512 * 512) {
        int row = i >> 9, k = i & 511;            // row = h*64 + n
        int h = row >> 6, n = row & 63;
        v = Ws[((size_t)h * 512 + k) * 64 + n];
        p = g_bt1 + i;
    } else if (i < 512 * 512 + 256 * 512) {
        int j = i - 512 * 512;
        int n = j >> 9, k = j & 511;
        v = (n < 128) ? muW[(size_t)k * 128 + n]
                      : lvW[(size_t)k * 128 + (n - 128)];
        p = g_bt2 + j;
    } else return;
    *p = __float2half_rn(v);
}

// ---------------- HMMA fp16 GEMM, 128x128 tile, C fp16 ---------------------
// Stage: A 16K | B 16K = 32KB; 2 stages = 64KB.
#define KC 64
#define STAGE 32768

__device__ __forceinline__ void load_chunk(
    unsigned st, const __half* __restrict__ A, const __half* __restrict__ B,
    int m0, int k0, int M, int tid)
{
#pragma unroll
    for (int it = 0; it < 4; it++) {
        int idx = it * 256 + tid;
        int r = idx >> 3, c = idx & 7;
        unsigned d = st + (unsigned)((r << 7) + (((c ^ (r & 7)) & 7) << 4));
        int grow = m0 + r;
        int sz = (grow < M) ? 16 : 0;
        if (grow >= M) grow = M - 1;
        cp16(d,         A + (size_t)grow * 512 + k0 + c * 8, sz);
        cp16(d + 16384, B + (size_t)r * 512 + k0 + c * 8, 16);
    }
}

__global__ __launch_bounds__(256) void gemm_tc(
    const __half* __restrict__ A, const __half* __restrict__ Bg,
    __half* __restrict__ C, int M, int ldc)
{
    extern __shared__ char smem[];
    const unsigned sbase = smem_u32(smem);
    const int tid = threadIdx.x, lane = tid & 31, wid = tid >> 5;
    const int m0 = blockIdx.y * 128;
    const int nb = blockIdx.x * 128;
    const __half* B = Bg + (size_t)nb * 512;
    const int wm = (wid & 3) * 32, wn = (wid >> 2) * 64;

    float acc[2][8][4];
#pragma unroll
    for (int i = 0; i < 2; i++)
#pragma unroll
        for (int j = 0; j < 8; j++)
#pragma unroll
            for (int q = 0; q < 4; q++) acc[i][j][q] = 0.f;

    load_chunk(sbase,         A, B, m0, 0,  M, tid);
    cp_commit();
    load_chunk(sbase + STAGE, A, B, m0, KC, M, tid);
    cp_commit();

    for (int kc = 0; kc < 8; kc++) {
        if (kc < 7)
            asm volatile("cp.async.wait_group 1;" ::: "memory");
        else
            asm volatile("cp.async.wait_group 0;" ::: "memory");
        __syncthreads();
        const unsigned st = sbase + (kc & 1) * STAGE;
#pragma unroll
        for (int kk = 0; kk < 4; kk++) {
            const int k = kk * 16;
            int ar = lane & 15;
            int ac = k + ((lane >> 4) << 3);
            unsigned ah[2][4];
            ldsm4(ah[0][0], ah[0][1], ah[0][2], ah[0][3], st + aoff(wm + ar, ac));
            ldsm4(ah[1][0], ah[1][1], ah[1][2], ah[1][3], st + aoff(wm + 16 + ar, ac));
            int br = (lane & 7) + ((lane >> 4) << 3);
            int bc = k + (((lane >> 3) & 1) << 3);
            unsigned b[8][2];
#pragma unroll
            for (int q = 0; q < 4; q++)
                ldsm4(b[2*q][0], b[2*q][1], b[2*q+1][0], b[2*q+1][1],
                      st + 16384 + aoff(wn + 16 * q + br, bc));
#pragma unroll
            for (int mt = 0; mt < 2; mt++)
#pragma unroll
                for (int nt = 0; nt < 8; nt++)
                    mma16816(acc[mt][nt], ah[mt], b[nt]);
        }
        __syncthreads();
        if (kc + 2 < 8) {
            load_chunk(sbase + (kc & 1) * STAGE, A, B, m0, (kc + 2) * KC, M, tid);
            cp_commit();
        }
    }

#pragma unroll
    for (int mt = 0; mt < 2; mt++) {
        int r0 = m0 + wm + mt * 16 + (lane >> 2);
#pragma unroll
        for (int nt = 0; nt < 8; nt++) {
            int c0 = nb + wn + nt * 8 + (lane & 3) * 2;
            if (r0 < M)
                *(__half2*)&C[(size_t)r0 * ldc + c0] =
                    __floats2half2_rn(acc[mt][nt][0], acc[mt][nt][1]);
            if (r0 + 8 < M)
                *(__half2*)&C[(size_t)(r0 + 8) * ldc + c0] =
                    __floats2half2_rn(acc[mt][nt][2], acc[mt][nt][3]);
        }
    }
}

// ---------------- layer-1 attention scalars (fp16 h) ----------------
__global__ __launch_bounds__(256) void scalars1_kernel(const float* __restrict__ As) {
    int n = blockIdx.x;
    int w = threadIdx.x >> 5, lane = threadIdx.x & 31;
    const __half2* hr = (const __half2*)(g_hh + (size_t)n * X2DIM + w * NHID);
    float2 f = __half22float2(hr[lane]);              // cols 2*lane, 2*lane+1
    const float* a = As + w * 2 * NHID;
    float d1 = f.x * a[2 * lane]      + f.y * a[2 * lane + 1];
    float d2 = f.x * a[64 + 2 * lane] + f.y * a[64 + 2 * lane + 1];
#pragma unroll
    for (int o = 16; o; o >>= 1) {
        d1 += __shfl_down_sync(0xffffffffu, d1, o);
        d2 += __shfl_down_sync(0xffffffffu, d2, o);
    }
    if (lane == 0) { g_s1[n * 8 + w] = d1; g_s2[n * 8 + w] = d2; }
}

// ---------------- layer-1 aggregation: warp-per-node, fp16 gather ----------
__global__ __launch_bounds__(256) void agg1_kernel(int N) {
    int n = (blockIdx.x * 256 + threadIdx.x) >> 5;
    if (n >= N) return;
    const int lane = threadIdx.x & 31;
    const int le = lane >> 3, hh = lane & 7;   // weight phase: edge-in-4, head
    const int hme = lane >> 2;                 // my head for gather/denominator
    const int beg = g_rowptr[n];
    const int deg = g_rowptr[n + 1] - beg;

    const float s1v = g_s1[n * 8 + hh];
    float acc[16];
#pragma unroll
    for (int i = 0; i < 16; i++) acc[i] = 0.f;
    float den = 0.f;

    for (int eb = 0; eb < deg; eb += 4) {
        const int cnt = min(4, deg - eb);
        int d_le = g_col[beg + ((le < cnt) ? (eb + le) : 0)];
        float logit = s1v + g_s2[d_le * 8 + hh];
        float lr = logit > 0.f ? logit : 0.2f * logit;
        float w_le = __expf(-lr);
#pragma unroll 4
        for (int e = 0; e < cnt; e++) {
            int   d = __shfl_sync(0xffffffffu, d_le, e << 3);
            float w = __shfl_sync(0xffffffffu, w_le, (e << 3) + hme);
            const uint4* hr = (const uint4*)(g_hh + (size_t)d * X2DIM) + lane * 2;
            uint4 pa = hr[0], pb = hr[1];
            const __half2* ha = (const __half2*)&pa;
            const __half2* hb = (const __half2*)&pb;
#pragma unroll
            for (int j = 0; j < 4; j++) {
                float2 fa = __half22float2(ha[j]);
                float2 fb = __half22float2(hb[j]);
                acc[2*j]     += w * fa.x; acc[2*j + 1] += w * fa.y;
                acc[8 + 2*j] += w * fb.x; acc[8 + 2*j + 1] += w * fb.y;
            }
            den += w;
        }
    }

    const float inv = 1.f / den;
    __half hi[16];
#pragma unroll
    for (int i = 0; i < 16; i++) {
        float t = acc[i] * inv;
        t = t > 0.f ? t : expm1f(t);
        hi[i] = __float2half_rn(t);
    }
    size_t o = (size_t)n * X2DIM + lane * 16;
    ((uint4*)(g_x2h + o))[0] = *(uint4*)(hi);
    ((uint4*)(g_x2h + o))[1] = *(uint4*)(hi + 8);
}

// ---------------- layer-2 attention scalars (fp16 hml) ----------------
__global__ __launch_bounds__(128) void scalars2_kernel(
    const float* __restrict__ mua, const float* __restrict__ lva)
{
    int n = blockIdx.x, t = threadIdx.x;
    float hmu = __half2float(g_hml[(size_t)n * 256 + t]);
    float hlv = __half2float(g_hml[(size_t)n * 256 + 128 + t]);
    float p0 = hmu * mua[t];
    float p1 = hmu * mua[128 + t];
    float p2 = hlv * lva[t];
    float p3 = hlv * lva[128 + t];
#pragma unroll
    for (int o = 16; o; o >>= 1) {
        p0 += __shfl_down_sync(0xffffffffu, p0, o);
        p1 += __shfl_down_sync(0xffffffffu, p1, o);
        p2 += __shfl_down_sync(0xffffffffu, p2, o);
        p3 += __shfl_down_sync(0xffffffffu, p3, o);
    }
    __shared__ float red[4][4];
    int w = t >> 5, lane = t & 31;
    if (lane == 0) { red[w][0] = p0; red[w][1] = p1; red[w][2] = p2; red[w][3] = p3; }
    __syncthreads();
    if (t == 0) {
        g_smu1[n] = red[0][0] + red[1][0] + red[2][0] + red[3][0];
        g_smu2[n] = red[0][1] + red[1][1] + red[2][1] + red[3][1];
        g_slv1[n] = red[0][2] + red[1][2] + red[2][2] + red[3][2];
        g_slv2[n] = red[0][3] + red[1][3] + red[2][3] + red[3][3];
    }
}

// ---------------- layer-2 aggregation: warp-per-node, fp16 gather ----------
__global__ __launch_bounds__(256) void agg2_kernel(
    const float* __restrict__ eps, float* __restrict__ out, int N)
{
    int n = (blockIdx.x * 256 + threadIdx.x) >> 5;
    if (n >= N) return;
    const int lane = threadIdx.x & 31;
    const int beg = g_rowptr[n];
    const int deg = g_rowptr[n + 1] - beg;
    const float bmu = g_smu1[n], blv = g_slv1[n];

    float amu[4] = {0,0,0,0}, alv[4] = {0,0,0,0};
    float dmu = 0.f, dlv = 0.f;

    for (int eb = 0; eb < deg; eb += 32) {
        const int cnt = min(32, deg - eb);
        int d_l = g_col[beg + ((lane < cnt) ? (eb + lane) : 0)];
        float lmu = bmu + g_smu2[d_l];
        float llv = blv + g_slv2[d_l];
        lmu = lmu > 0.f ? lmu : 0.2f * lmu;
        llv = llv > 0.f ? llv : 0.2f * llv;
        float wmu_l = __expf(-lmu);
        float wlv_l = __expf(-llv);
#pragma unroll 4
        for (int e = 0; e < cnt; e++) {
            int   d   = __shfl_sync(0xffffffffu, d_l,   e);
            float wmu = __shfl_sync(0xffffffffu, wmu_l, e);
            float wlv = __shfl_sync(0xffffffffu, wlv_l, e);
            const __half* base = g_hml + (size_t)d * 256;
            uint2 pm = *(const uint2*)(base + lane * 4);
            uint2 pl = *(const uint2*)(base + 128 + lane * 4);
            const __half2* hm = (const __half2*)&pm;
            const __half2* hl = (const __half2*)&pl;
            float2 m0 = __half22float2(hm[0]), m1 = __half22float2(hm[1]);
            float2 l0 = __half22float2(hl[0]), l1 = __half22float2(hl[1]);
            amu[0] += wmu * m0.x; amu[1] += wmu * m0.y;
            amu[2] += wmu * m1.x; amu[3] += wmu * m1.y;
            alv[0] += wlv * l0.x; alv[1] += wlv * l0.y;
            alv[2] += wlv * l1.x; alv[3] += wlv * l1.y;
            dmu += wmu; dlv += wlv;
        }
    }

    const float imu = 1.f / dmu, ilv = 1.f / dlv;
    float4 mu = make_float4(amu[0]*imu, amu[1]*imu, amu[2]*imu, amu[3]*imu);
    float4 lv = make_float4(alv[0]*ilv, alv[1]*ilv, alv[2]*ilv, alv[3]*ilv);
    float4 ev = *(const float4*)(eps + (size_t)n * NOUT + lane * 4);
    float4 z  = make_float4(ev.x * expf(lv.x) + mu.x,
                            ev.y * expf(lv.y) + mu.y,
                            ev.z * expf(lv.z) + mu.z,
                            ev.w * expf(lv.w) + mu.w);
    size_t NO = (size_t)N * NOUT;
    size_t o  = (size_t)n * NOUT + lane * 4;
    *(float4*)(out + o)          = z;
    *(float4*)(out + NO + o)     = mu;
    *(float4*)(out + 2 * NO + o) = lv;
}

// ---------------- host orchestration ----------------
extern "C" void kernel_launch(void* const* d_in, const int* in_sizes, int n_in,
                              void* d_out, int out_size)
{
    const float* x   = (const float*)d_in[0];
    const float* Ws  = (const float*)d_in[1];
    const float* As  = (const float*)d_in[2];
    const float* muW = (const float*)d_in[3];
    const float* mua = (const float*)d_in[4];
    const float* lvW = (const float*)d_in[5];
    const float* lva = (const float*)d_in[6];
    const float* eps = (const float*)d_in[7];
    const int*   ei  = (const int*)d_in[8];
    int E = in_sizes[8] / 2;
    int N = in_sizes[0] / NFEAT;
    float* out = (float*)d_out;

    __half *p_hh, *p_hml, *p_xh, *p_x2h, *p_bt1, *p_bt2;
    cudaGetSymbolAddress((void**)&p_hh,   g_hh);
    cudaGetSymbolAddress((void**)&p_hml,  g_hml);
    cudaGetSymbolAddress((void**)&p_xh,   g_xh);
    cudaGetSymbolAddress((void**)&p_x2h,  g_x2h);
    cudaGetSymbolAddress((void**)&p_bt1,  g_bt1);
    cudaGetSymbolAddress((void**)&p_bt2,  g_bt2);

    cudaFuncSetAttribute(gemm_tc, cudaFuncAttributeMaxDynamicSharedMemorySize,
                         2 * STAGE);

    int mtiles = (N + 127) / 128;
    int wblocks = (N + 7) / 8;     // warp-per-node kernels: 8 warps/block

    // gemm_tc (layer-1) kept at the ncu-profiled launch slot (#3)
    convert_x_kernel<<<(N * NFEAT / 4 + 255) / 256, 256>>>(x, N * NFEAT / 4);     // 0
    convert_w_kernel<<<(512 * 512 + 256 * 512 + 255) / 256, 256>>>(Ws, muW, lvW); // 1
    zero_kernel<<<(N + 255) / 256, 256>>>(N);                                     // 2
    gemm_tc<<<dim3(4, mtiles), 256, 2 * STAGE>>>(p_xh, p_bt1,                     // 3
                                                 p_hh, N, X2DIM);
    hist_kernel<<<(E + 255) / 256, 256>>>(ei, E);                                 // 4
    scan_kernel<<<1, 1024>>>(N);                                                  // 5
    fill_kernel<<<(E + 255) / 256, 256>>>(ei, E);                                 // 6
    scalars1_kernel<<<N, 256>>>(As);                                              // 7
    agg1_kernel<<<wblocks, 256>>>(N);                                             // 8
    gemm_tc<<<dim3(2, mtiles), 256, 2 * STAGE>>>(p_x2h, p_bt2,                    // 9
                                                 p_hml, N, 256);
    scalars2_kernel<<<N, 128>>>(mua, lva);                                        // 10
    agg2_kernel<<<wblocks, 256>>>(eps, out, N);                                   // 11
}

// round 12
// speedup vs baseline: 2.1197x; 1.1456x over previous
#include <cuda_runtime.h>
#include <cuda_fp16.h>
#include <cstdint>

// ---------------- problem constants ----------------
#define N_NODES  50000
#define E_MAX    450000
#define NFEAT    512
#define NHID     64
#define NHEADS   8
#define NOUT     128
#define X2DIM    512

// ---------------- device scratch ----------------
__device__ __half g_hh [(size_t)N_NODES * X2DIM];   // layer-1 head features, fp16
__device__ __half g_hml[(size_t)N_NODES * 256];     // fp16: [:,0:128]=h_mu, [:,128:256]=h_lv
__device__ float g_s1  [N_NODES * NHEADS];
__device__ float g_s2  [N_NODES * NHEADS];
__device__ float g_smu1[N_NODES], g_smu2[N_NODES], g_slv1[N_NODES], g_slv2[N_NODES];
__device__ int   g_rowptr[N_NODES + 1];
__device__ int   g_col [E_MAX];
__device__ int   g_cnt [N_NODES];
__device__ int   g_cursor[N_NODES];

// fp16 activations (single limb), fp16 weights
__device__ __half g_xh [(size_t)N_NODES * NFEAT];
__device__ __half g_x2h[(size_t)N_NODES * X2DIM];
__device__ __half g_bt1[512 * 512];                 // Ws^T        [512,512]
__device__ __half g_bt2[256 * 512];                 // [muW;lvW]^T [256,512]

// ---------------- PTX helpers (target-generic, sm_80+) ----------------
__device__ __forceinline__ unsigned smem_u32(const void* p) {
    unsigned r;
    asm("{ .reg .u64 t; cvta.to.shared.u64 t, %1; cvt.u32.u64 %0, t; }"
        : "=r"(r) : "l"(p));
    return r;
}
__device__ __forceinline__ void cp16(unsigned dst, const void* src, int srcsz) {
    asm volatile("cp.async.cg.shared.global [%0], [%1], 16, %2;"
                 :: "r"(dst), "l"(src), "r"(srcsz) : "memory");
}
__device__ __forceinline__ void cp_commit() {
    asm volatile("cp.async.commit_group;" ::: "memory");
}
__device__ __forceinline__ void ldsm4(unsigned& r0, unsigned& r1, unsigned& r2,
                                      unsigned& r3, unsigned a) {
    asm volatile("ldmatrix.sync.aligned.m8n8.x4.shared.b16 {%0,%1,%2,%3}, [%4];"
                 : "=r"(r0), "=r"(r1), "=r"(r2), "=r"(r3) : "r"(a));
}
__device__ __forceinline__ void mma16816(float* d, const unsigned* a, const unsigned* b) {
    asm volatile(
        "mma.sync.aligned.m16n8k16.row.col.f32.f16.f16.f32 "
        "{%0,%1,%2,%3}, {%4,%5,%6,%7}, {%8,%9}, {%0,%1,%2,%3};"
        : "+f"(d[0]), "+f"(d[1]), "+f"(d[2]), "+f"(d[3])
        : "r"(a[0]), "r"(a[1]), "r"(a[2]), "r"(a[3]), "r"(b[0]), "r"(b[1]));
}
// swizzled byte offset inside a tile whose rows are 64 fp16 = 128B
__device__ __forceinline__ unsigned aoff(int r, int k) {
    return (unsigned)((r << 7) + (((((k >> 3) ^ r) & 7)) << 4) + ((k & 7) << 1));
}

// ---------------- CSR construction ----------------
__global__ void zero_kernel(int n) {
    int i = blockIdx.x * blockDim.x + threadIdx.x;
    if (i < n) { g_cnt[i] = 0; g_cursor[i] = 0; }
}
__global__ void hist_kernel(const int* __restrict__ ei, int E) {
    int e = blockIdx.x * blockDim.x + threadIdx.x;
    if (e < E) atomicAdd(&g_cnt[ei[e]], 1);
}
// one-pass scan: 1024 threads, each owns a contiguous chunk
__global__ __launch_bounds__(1024) void scan_kernel(int n) {
    __shared__ int sh[1024];
    const int t = threadIdx.x;
    const int per = (n + 1023) / 1024;
    const int lo = min(t * per, n), hi = min(lo + per, n);
    int sum = 0;
    for (int i = lo; i < hi; i++) sum += g_cnt[i];
    sh[t] = sum;
    __syncthreads();
    for (int off = 1; off < 1024; off <<= 1) {
        int v = (t >= off) ? sh[t - off] : 0;
        __syncthreads();
        sh[t] += v;
        __syncthreads();
    }
    int run = sh[t] - sum;          // exclusive offset for this chunk
    for (int i = lo; i < hi; i++) {
        g_rowptr[i] = run;
        run += g_cnt[i];
    }
    if (t == 1023) g_rowptr[n] = sh[1023];
}
__global__ void fill_kernel(const int* __restrict__ ei, int E) {
    int e = blockIdx.x * blockDim.x + threadIdx.x;
    if (e < E) {
        int s = ei[e];
        int d = ei[E + e];
        int p = atomicAdd(&g_cursor[s], 1);
        g_col[g_rowptr[s] + p] = d;
    }
}

// ---------------- conversions ----------------
__global__ void convert_x_kernel(const float* __restrict__ x, int n4) {
    int i = blockIdx.x * blockDim.x + threadIdx.x;
    if (i >= n4) return;
    float4 v = ((const float4*)x)[i];
    ((__half2*)g_xh)[i * 2]     = __floats2half2_rn(v.x, v.y);
    ((__half2*)g_xh)[i * 2 + 1] = __floats2half2_rn(v.z, v.w);
}

__global__ void convert_w_kernel(const float* __restrict__ Ws,
                                 const float* __restrict__ muW,
                                 const float* __restrict__ lvW) {
    int i = blockIdx.x * blockDim.x + threadIdx.x;
    float v;
    __half* p;
    if (i < 512 * 512) {
        int row = i >> 9, k = i & 511;            // row = h*64 + n
        int h = row >> 6, n = row & 63;
        v = Ws[((size_t)h * 512 + k) * 64 + n];
        p = g_bt1 + i;
    } else if (i < 512 * 512 + 256 * 512) {
        int j = i - 512 * 512;
        int n = j >> 9, k = j & 511;
        v = (n < 128) ? muW[(size_t)k * 128 + n]
                      : lvW[(size_t)k * 128 + (n - 128)];
        p = g_bt2 + j;
    } else return;
    *p = __float2half_rn(v);
}

// ---------------- HMMA fp16 GEMM, 128x128 tile, 3-stage, 1 sync/chunk ------
// Stage: A 16K | B 16K = 32KB; 3 stages = 96KB -> 2 CTAs/SM.
#define KC 64
#define STAGE 32768
#define NSTAGE 3

__device__ __forceinline__ void load_chunk(
    unsigned st, const __half* __restrict__ A, const __half* __restrict__ B,
    int m0, int k0, int M, int tid)
{
#pragma unroll
    for (int it = 0; it < 4; it++) {
        int idx = it * 256 + tid;
        int r = idx >> 3, c = idx & 7;
        unsigned d = st + (unsigned)((r << 7) + (((c ^ (r & 7)) & 7) << 4));
        int grow = m0 + r;
        int sz = (grow < M) ? 16 : 0;
        if (grow >= M) grow = M - 1;
        cp16(d,         A + (size_t)grow * 512 + k0 + c * 8, sz);
        cp16(d + 16384, B + (size_t)r * 512 + k0 + c * 8, 16);
    }
}

__global__ __launch_bounds__(256) void gemm_tc(
    const __half* __restrict__ A, const __half* __restrict__ Bg,
    __half* __restrict__ C, int M, int ldc)
{
    extern __shared__ char smem[];
    const unsigned sbase = smem_u32(smem);
    const int tid = threadIdx.x, lane = tid & 31, wid = tid >> 5;
    const int m0 = blockIdx.y * 128;
    const int nb = blockIdx.x * 128;
    const __half* B = Bg + (size_t)nb * 512;
    const int wm = (wid & 3) * 32, wn = (wid >> 2) * 64;

    float acc[2][8][4];
#pragma unroll
    for (int i = 0; i < 2; i++)
#pragma unroll
        for (int j = 0; j < 8; j++)
#pragma unroll
            for (int q = 0; q < 4; q++) acc[i][j][q] = 0.f;

    load_chunk(sbase,         A, B, m0, 0,  M, tid);
    cp_commit();
    load_chunk(sbase + STAGE, A, B, m0, KC, M, tid);
    cp_commit();

    for (int kc = 0; kc < 8; kc++) {
        if (kc < 7)
            asm volatile("cp.async.wait_group 1;" ::: "memory");
        else
            asm volatile("cp.async.wait_group 0;" ::: "memory");
        __syncthreads();                 // single sync: chunk kc ready, buffer
                                         // (kc+2)%3 fully consumed by all warps
        if (kc + 2 < 8) {
            load_chunk(sbase + ((kc + 2) % NSTAGE) * STAGE, A, B,
                       m0, (kc + 2) * KC, M, tid);
            cp_commit();
        }
        const unsigned st = sbase + (kc % NSTAGE) * STAGE;
#pragma unroll
        for (int kk = 0; kk < 4; kk++) {
            const int k = kk * 16;
            int ar = lane & 15;
            int ac = k + ((lane >> 4) << 3);
            unsigned ah[2][4];
            ldsm4(ah[0][0], ah[0][1], ah[0][2], ah[0][3], st + aoff(wm + ar, ac));
            ldsm4(ah[1][0], ah[1][1], ah[1][2], ah[1][3], st + aoff(wm + 16 + ar, ac));
            int br = (lane & 7) + ((lane >> 4) << 3);
            int bc = k + (((lane >> 3) & 1) << 3);
            unsigned b[8][2];
#pragma unroll
            for (int q = 0; q < 4; q++)
                ldsm4(b[2*q][0], b[2*q][1], b[2*q+1][0], b[2*q+1][1],
                      st + 16384 + aoff(wn + 16 * q + br, bc));
#pragma unroll
            for (int mt = 0; mt < 2; mt++)
#pragma unroll
                for (int nt = 0; nt < 8; nt++)
                    mma16816(acc[mt][nt], ah[mt], b[nt]);
        }
    }

#pragma unroll
    for (int mt = 0; mt < 2; mt++) {
        int r0 = m0 + wm + mt * 16 + (lane >> 2);
#pragma unroll
        for (int nt = 0; nt < 8; nt++) {
            int c0 = nb + wn + nt * 8 + (lane & 3) * 2;
            if (r0 < M)
                *(__half2*)&C[(size_t)r0 * ldc + c0] =
                    __floats2half2_rn(acc[mt][nt][0], acc[mt][nt][1]);
            if (r0 + 8 < M)
                *(__half2*)&C[(size_t)(r0 + 8) * ldc + c0] =
                    __floats2half2_rn(acc[mt][nt][2], acc[mt][nt][3]);
        }
    }
}

// ---------------- layer-1 attention scalars (fp16 h) ----------------
__global__ __launch_bounds__(256) void scalars1_kernel(const float* __restrict__ As) {
    int n = blockIdx.x;
    int w = threadIdx.x >> 5, lane = threadIdx.x & 31;
    const __half2* hr = (const __half2*)(g_hh + (size_t)n * X2DIM + w * NHID);
    float2 f = __half22float2(hr[lane]);              // cols 2*lane, 2*lane+1
    const float* a = As + w * 2 * NHID;
    float d1 = f.x * a[2 * lane]      + f.y * a[2 * lane + 1];
    float d2 = f.x * a[64 + 2 * lane] + f.y * a[64 + 2 * lane + 1];
#pragma unroll
    for (int o = 16; o; o >>= 1) {
        d1 += __shfl_down_sync(0xffffffffu, d1, o);
        d2 += __shfl_down_sync(0xffffffffu, d2, o);
    }
    if (lane == 0) { g_s1[n * 8 + w] = d1; g_s2[n * 8 + w] = d2; }
}

// ---------------- layer-1 aggregation: warp-per-node, fp16 gather ----------
__global__ __launch_bounds__(256) void agg1_kernel(int N) {
    int n = (blockIdx.x * 256 + threadIdx.x) >> 5;
    if (n >= N) return;
    const int lane = threadIdx.x & 31;
    const int le = lane >> 3, hh = lane & 7;   // weight phase: edge-in-4, head
    const int hme = lane >> 2;                 // my head for gather/denominator
    const int beg = g_rowptr[n];
    const int deg = g_rowptr[n + 1] - beg;

    const float s1v = g_s1[n * 8 + hh];
    float acc[16];
#pragma unroll
    for (int i = 0; i < 16; i++) acc[i] = 0.f;
    float den = 0.f;

    for (int eb = 0; eb < deg; eb += 4) {
        const int cnt = min(4, deg - eb);
        int d_le = g_col[beg + ((le < cnt) ? (eb + le) : 0)];
        float logit = s1v + g_s2[d_le * 8 + hh];
        float lr = logit > 0.f ? logit : 0.2f * logit;
        float w_le = __expf(-lr);
#pragma unroll 4
        for (int e = 0; e < cnt; e++) {
            int   d = __shfl_sync(0xffffffffu, d_le, e << 3);
            float w = __shfl_sync(0xffffffffu, w_le, (e << 3) + hme);
            const uint4* hr = (const uint4*)(g_hh + (size_t)d * X2DIM) + lane * 2;
            uint4 pa = hr[0], pb = hr[1];
            const __half2* ha = (const __half2*)&pa;
            const __half2* hb = (const __half2*)&pb;
#pragma unroll
            for (int j = 0; j < 4; j++) {
                float2 fa = __half22float2(ha[j]);
                float2 fb = __half22float2(hb[j]);
                acc[2*j]     += w * fa.x; acc[2*j + 1] += w * fa.y;
                acc[8 + 2*j] += w * fb.x; acc[8 + 2*j + 1] += w * fb.y;
            }
            den += w;
        }
    }

    const float inv = 1.f / den;
    __half hi[16];
#pragma unroll
    for (int i = 0; i < 16; i++) {
        float t = acc[i] * inv;
        t = t > 0.f ? t : expm1f(t);
        hi[i] = __float2half_rn(t);
    }
    size_t o = (size_t)n * X2DIM + lane * 16;
    ((uint4*)(g_x2h + o))[0] = *(uint4*)(hi);
    ((uint4*)(g_x2h + o))[1] = *(uint4*)(hi + 8);
}

// ---------------- layer-2 attention scalars (fp16 hml) ----------------
__global__ __launch_bounds__(128) void scalars2_kernel(
    const float* __restrict__ mua, const float* __restrict__ lva)
{
    int n = blockIdx.x, t = threadIdx.x;
    float hmu = __half2float(g_hml[(size_t)n * 256 + t]);
    float hlv = __half2float(g_hml[(size_t)n * 256 + 128 + t]);
    float p0 = hmu * mua[t];
    float p1 = hmu * mua[128 + t];
    float p2 = hlv * lva[t];
    float p3 = hlv * lva[128 + t];
#pragma unroll
    for (int o = 16; o; o >>= 1) {
        p0 += __shfl_down_sync(0xffffffffu, p0, o);
        p1 += __shfl_down_sync(0xffffffffu, p1, o);
        p2 += __shfl_down_sync(0xffffffffu, p2, o);
        p3 += __shfl_down_sync(0xffffffffu, p3, o);
    }
    __shared__ float red[4][4];
    int w = t >> 5, lane = t & 31;
    if (lane == 0) { red[w][0] = p0; red[w][1] = p1; red[w][2] = p2; red[w][3] = p3; }
    __syncthreads();
    if (t == 0) {
        g_smu1[n] = red[0][0] + red[1][0] + red[2][0] + red[3][0];
        g_smu2[n] = red[0][1] + red[1][1] + red[2][1] + red[3][1];
        g_slv1[n] = red[0][2] + red[1][2] + red[2][2] + red[3][2];
        g_slv2[n] = red[0][3] + red[1][3] + red[2][3] + red[3][3];
    }
}

// ---------------- layer-2 aggregation: warp-per-node, fp16 gather ----------
__global__ __launch_bounds__(256) void agg2_kernel(
    const float* __restrict__ eps, float* __restrict__ out, int N)
{
    int n = (blockIdx.x * 256 + threadIdx.x) >> 5;
    if (n >= N) return;
    const int lane = threadIdx.x & 31;
    const int beg = g_rowptr[n];
    const int deg = g_rowptr[n + 1] - beg;
    const float bmu = g_smu1[n], blv = g_slv1[n];

    float amu[4] = {0,0,0,0}, alv[4] = {0,0,0,0};
    float dmu = 0.f, dlv = 0.f;

    for (int eb = 0; eb < deg; eb += 32) {
        const int cnt = min(32, deg - eb);
        int d_l = g_col[beg + ((lane < cnt) ? (eb + lane) : 0)];
        float lmu = bmu + g_smu2[d_l];
        float llv = blv + g_slv2[d_l];
        lmu = lmu > 0.f ? lmu : 0.2f * lmu;
        llv = llv > 0.f ? llv : 0.2f * llv;
        float wmu_l = __expf(-lmu);
        float wlv_l = __expf(-llv);
#pragma unroll 4
        for (int e = 0; e < cnt; e++) {
            int   d   = __shfl_sync(0xffffffffu, d_l,   e);
            float wmu = __shfl_sync(0xffffffffu, wmu_l, e);
            float wlv = __shfl_sync(0xffffffffu, wlv_l, e);
            const __half* base = g_hml + (size_t)d * 256;
            uint2 pm = *(const uint2*)(base + lane * 4);
            uint2 pl = *(const uint2*)(base + 128 + lane * 4);
            const __half2* hm = (const __half2*)&pm;
            const __half2* hl = (const __half2*)&pl;
            float2 m0 = __half22float2(hm[0]), m1 = __half22float2(hm[1]);
            float2 l0 = __half22float2(hl[0]), l1 = __half22float2(hl[1]);
            amu[0] += wmu * m0.x; amu[1] += wmu * m0.y;
            amu[2] += wmu * m1.x; amu[3] += wmu * m1.y;
            alv[0] += wlv * l0.x; alv[1] += wlv * l0.y;
            alv[2] += wlv * l1.x; alv[3] += wlv * l1.y;
            dmu += wmu; dlv += wlv;
        }
    }

    const float imu = 1.f / dmu, ilv = 1.f / dlv;
    float4 mu = make_float4(amu[0]*imu, amu[1]*imu, amu[2]*imu, amu[3]*imu);
    float4 lv = make_float4(alv[0]*ilv, alv[1]*ilv, alv[2]*ilv, alv[3]*ilv);
    float4 ev = *(const float4*)(eps + (size_t)n * NOUT + lane * 4);
    float4 z  = make_float4(ev.x * expf(lv.x) + mu.x,
                            ev.y * expf(lv.y) + mu.y,
                            ev.z * expf(lv.z) + mu.z,
                            ev.w * expf(lv.w) + mu.w);
    size_t NO = (size_t)N * NOUT;
    size_t o  = (size_t)n * NOUT + lane * 4;
    *(float4*)(out + o)          = z;
    *(float4*)(out + NO + o)     = mu;
    *(float4*)(out + 2 * NO + o) = lv;
}

// ---------------- host orchestration ----------------
extern "C" void kernel_launch(void* const* d_in, const int* in_sizes, int n_in,
                              void* d_out, int out_size)
{
    const float* x   = (const float*)d_in[0];
    const float* Ws  = (const float*)d_in[1];
    const float* As  = (const float*)d_in[2];
    const float* muW = (const float*)d_in[3];
    const float* mua = (const float*)d_in[4];
    const float* lvW = (const float*)d_in[5];
    const float* lva = (const float*)d_in[6];
    const float* eps = (const float*)d_in[7];
    const int*   ei  = (const int*)d_in[8];
    int E = in_sizes[8] / 2;
    int N = in_sizes[0] / NFEAT;
    float* out = (float*)d_out;

    __half *p_hh, *p_hml, *p_xh, *p_x2h, *p_bt1, *p_bt2;
    cudaGetSymbolAddress((void**)&p_hh,   g_hh);
    cudaGetSymbolAddress((void**)&p_hml,  g_hml);
    cudaGetSymbolAddress((void**)&p_xh,   g_xh);
    cudaGetSymbolAddress((void**)&p_x2h,  g_x2h);
    cudaGetSymbolAddress((void**)&p_bt1,  g_bt1);
    cudaGetSymbolAddress((void**)&p_bt2,  g_bt2);

    cudaFuncSetAttribute(gemm_tc, cudaFuncAttributeMaxDynamicSharedMemorySize,
                         NSTAGE * STAGE);

    // side stream + events for graph-fork (created once; host-side resources)
    static cudaStream_t sB = nullptr;
    static cudaEvent_t eFork = nullptr, eJoin = nullptr;
    if (!sB) {
        cudaStreamCreateWithFlags(&sB, cudaStreamNonBlocking);
        cudaEventCreateWithFlags(&eFork, cudaEventDisableTiming);
        cudaEventCreateWithFlags(&eJoin, cudaEventDisableTiming);
    }

    int mtiles = (N + 127) / 128;
    int wblocks = (N + 7) / 8;     // warp-per-node kernels: 8 warps/block

    // fork: CSR chain on side stream, overlapped with convert+gemm1+scalars1
    cudaEventRecord(eFork, 0);
    cudaStreamWaitEvent(sB, eFork, 0);

    convert_x_kernel<<<(N * NFEAT / 4 + 255) / 256, 256>>>(x, N * NFEAT / 4);       // 0
    convert_w_kernel<<<(512 * 512 + 256 * 512 + 255) / 256, 256>>>(Ws, muW, lvW);   // 1
    zero_kernel<<<(N + 255) / 256, 256, 0, sB>>>(N);                                 // 2
    gemm_tc<<<dim3(4, mtiles), 256, NSTAGE * STAGE>>>(p_xh, p_bt1, p_hh, N, X2DIM);  // 3
    hist_kernel<<<(E + 255) / 256, 256, 0, sB>>>(ei, E);                             // 4
    scan_kernel<<<1, 1024, 0, sB>>>(N);                                              // 5
    fill_kernel<<<(E + 255) / 256, 256, 0, sB>>>(ei, E);                             // 6
    cudaEventRecord(eJoin, sB);

    scalars1_kernel<<<N, 256>>>(As);                                                 // 7
    cudaStreamWaitEvent(0, eJoin, 0);   // join: agg1 needs CSR + scalars1
    agg1_kernel<<<wblocks, 256>>>(N);                                                // 8
    gemm_tc<<<dim3(2, mtiles), 256, NSTAGE * STAGE>>>(p_x2h, p_bt2, p_hml, N, 256);  // 9
    scalars2_kernel<<<N, 128>>>(mua, lva);                                           // 10
    agg2_kernel<<<wblocks, 256>>>(eps, out, N);                                      // 11
}

// round 13
// speedup vs baseline: 2.4858x; 1.1727x over previous
#include <cuda_runtime.h>
#include <cuda_fp16.h>
#include <cstdint>

// ---------------- problem constants ----------------
#define N_NODES  50000
#define E_MAX    450000
#define NFEAT    512
#define NHID     64
#define NHEADS   8
#define NOUT     128
#define X2DIM    512

// ---------------- device scratch ----------------
__device__ __half g_hh [(size_t)N_NODES * X2DIM];   // layer-1 head features, fp16
__device__ __half g_hml[(size_t)N_NODES * 256];     // fp16: [:,0:128]=h_mu, [:,128:256]=h_lv
__device__ float g_s1  [N_NODES * NHEADS];
__device__ float g_s2  [N_NODES * NHEADS];
__device__ float g_smu1[N_NODES], g_smu2[N_NODES], g_slv1[N_NODES], g_slv2[N_NODES];
__device__ int   g_rowptr[N_NODES + 1];
__device__ int   g_col [E_MAX];
__device__ int   g_cnt [N_NODES];
__device__ int   g_cursor[N_NODES];

// fp16 activations (single limb), fp16 weights
__device__ __half g_xh [(size_t)N_NODES * NFEAT];
__device__ __half g_x2h[(size_t)N_NODES * X2DIM];
__device__ __half g_bt1[512 * 512];                 // Ws^T        [512,512]
__device__ __half g_bt2[256 * 512];                 // [muW;lvW]^T [256,512]

// ---------------- PTX helpers (target-generic, sm_80+) ----------------
__device__ __forceinline__ unsigned smem_u32(const void* p) {
    unsigned r;
    asm("{ .reg .u64 t; cvta.to.shared.u64 t, %1; cvt.u32.u64 %0, t; }"
        : "=r"(r) : "l"(p));
    return r;
}
__device__ __forceinline__ void cp16(unsigned dst, const void* src, int srcsz) {
    asm volatile("cp.async.cg.shared.global [%0], [%1], 16, %2;"
                 :: "r"(dst), "l"(src), "r"(srcsz) : "memory");
}
__device__ __forceinline__ void cp_commit() {
    asm volatile("cp.async.commit_group;" ::: "memory");
}
__device__ __forceinline__ void ldsm4(unsigned& r0, unsigned& r1, unsigned& r2,
                                      unsigned& r3, unsigned a) {
    asm volatile("ldmatrix.sync.aligned.m8n8.x4.shared.b16 {%0,%1,%2,%3}, [%4];"
                 : "=r"(r0), "=r"(r1), "=r"(r2), "=r"(r3) : "r"(a));
}
__device__ __forceinline__ void mma16816(float* d, const unsigned* a, const unsigned* b) {
    asm volatile(
        "mma.sync.aligned.m16n8k16.row.col.f32.f16.f16.f32 "
        "{%0,%1,%2,%3}, {%4,%5,%6,%7}, {%8,%9}, {%0,%1,%2,%3};"
        : "+f"(d[0]), "+f"(d[1]), "+f"(d[2]), "+f"(d[3])
        : "r"(a[0]), "r"(a[1]), "r"(a[2]), "r"(a[3]), "r"(b[0]), "r"(b[1]));
}
// swizzled byte offset inside a tile whose rows are 64 fp16 = 128B
__device__ __forceinline__ unsigned aoff(int r, int k) {
    return (unsigned)((r << 7) + (((((k >> 3) ^ r) & 7)) << 4) + ((k & 7) << 1));
}

// ---------------- CSR construction ----------------
__global__ void zero_kernel(int n) {
    int i = blockIdx.x * blockDim.x + threadIdx.x;
    if (i < n) {
        g_cnt[i] = 0; g_cursor[i] = 0;
        g_smu1[i] = 0.f; g_smu2[i] = 0.f;
        g_slv1[i] = 0.f; g_slv2[i] = 0.f;
    }
}
__global__ void hist_kernel(const int* __restrict__ ei, int E) {
    int e = blockIdx.x * blockDim.x + threadIdx.x;
    if (e < E) atomicAdd(&g_cnt[ei[e]], 1);
}
// one-pass scan: 1024 threads, each owns a contiguous chunk
__global__ __launch_bounds__(1024) void scan_kernel(int n) {
    __shared__ int sh[1024];
    const int t = threadIdx.x;
    const int per = (n + 1023) / 1024;
    const int lo = min(t * per, n), hi = min(lo + per, n);
    int sum = 0;
    for (int i = lo; i < hi; i++) sum += g_cnt[i];
    sh[t] = sum;
    __syncthreads();
    for (int off = 1; off < 1024; off <<= 1) {
        int v = (t >= off) ? sh[t - off] : 0;
        __syncthreads();
        sh[t] += v;
        __syncthreads();
    }
    int run = sh[t] - sum;          // exclusive offset for this chunk
    for (int i = lo; i < hi; i++) {
        g_rowptr[i] = run;
        run += g_cnt[i];
    }
    if (t == 1023) g_rowptr[n] = sh[1023];
}
__global__ void fill_kernel(const int* __restrict__ ei, int E) {
    int e = blockIdx.x * blockDim.x + threadIdx.x;
    if (e < E) {
        int s = ei[e];
        int d = ei[E + e];
        int p = atomicAdd(&g_cursor[s], 1);
        g_col[g_rowptr[s] + p] = d;
    }
}

// ---------------- conversions ----------------
__global__ void convert_x_kernel(const float* __restrict__ x, int n4) {
    int i = blockIdx.x * blockDim.x + threadIdx.x;
    if (i >= n4) return;
    float4 v = ((const float4*)x)[i];
    ((__half2*)g_xh)[i * 2]     = __floats2half2_rn(v.x, v.y);
    ((__half2*)g_xh)[i * 2 + 1] = __floats2half2_rn(v.z, v.w);
}

__global__ void convert_w_kernel(const float* __restrict__ Ws,
                                 const float* __restrict__ muW,
                                 const float* __restrict__ lvW) {
    int i = blockIdx.x * blockDim.x + threadIdx.x;
    float v;
    __half* p;
    if (i < 512 * 512) {
        int row = i >> 9, k = i & 511;            // row = h*64 + n
        int h = row >> 6, n = row & 63;
        v = Ws[((size_t)h * 512 + k) * 64 + n];
        p = g_bt1 + i;
    } else if (i < 512 * 512 + 256 * 512) {
        int j = i - 512 * 512;
        int n = j >> 9, k = j & 511;
        v = (n < 128) ? muW[(size_t)k * 128 + n]
                      : lvW[(size_t)k * 128 + (n - 128)];
        p = g_bt2 + j;
    } else return;
    *p = __float2half_rn(v);
}

// ---------------- HMMA fp16 GEMM + fused attention-scalar epilogue ---------
// MODE 1: layer-1. C = g_hh; per-warp exact s1/s2 dots -> direct store.
// MODE 2: layer-2. C = g_hml; partial dots -> atomicAdd into g_smu*/g_slv*.
// Stage: A 16K | B 16K = 32KB; 3 stages = 96KB -> 2 CTAs/SM.
#define KC 64
#define STAGE 32768
#define NSTAGE 3

__device__ __forceinline__ void load_chunk(
    unsigned st, const __half* __restrict__ A, const __half* __restrict__ B,
    int m0, int k0, int M, int tid)
{
#pragma unroll
    for (int it = 0; it < 4; it++) {
        int idx = it * 256 + tid;
        int r = idx >> 3, c = idx & 7;
        unsigned d = st + (unsigned)((r << 7) + (((c ^ (r & 7)) & 7) << 4));
        int grow = m0 + r;
        int sz = (grow < M) ? 16 : 0;
        if (grow >= M) grow = M - 1;
        cp16(d,         A + (size_t)grow * 512 + k0 + c * 8, sz);
        cp16(d + 16384, B + (size_t)r * 512 + k0 + c * 8, 16);
    }
}

template <int MODE>
__global__ __launch_bounds__(256) void gemm_tc(
    const __half* __restrict__ A, const __half* __restrict__ Bg,
    __half* __restrict__ C, int M, int ldc,
    const float* __restrict__ av1, const float* __restrict__ av2)
{
    extern __shared__ char smem[];
    const unsigned sbase = smem_u32(smem);
    const int tid = threadIdx.x, lane = tid & 31, wid = tid >> 5;
    const int m0 = blockIdx.y * 128;
    const int nb = blockIdx.x * 128;
    const __half* B = Bg + (size_t)nb * 512;
    const int wm = (wid & 3) * 32, wn = (wid >> 2) * 64;

    float acc[2][8][4];
#pragma unroll
    for (int i = 0; i < 2; i++)
#pragma unroll
        for (int j = 0; j < 8; j++)
#pragma unroll
            for (int q = 0; q < 4; q++) acc[i][j][q] = 0.f;

    load_chunk(sbase,         A, B, m0, 0,  M, tid);
    cp_commit();
    load_chunk(sbase + STAGE, A, B, m0, KC, M, tid);
    cp_commit();

    for (int kc = 0; kc < 8; kc++) {
        if (kc < 7)
            asm volatile("cp.async.wait_group 1;" ::: "memory");
        else
            asm volatile("cp.async.wait_group 0;" ::: "memory");
        __syncthreads();
        if (kc + 2 < 8) {
            load_chunk(sbase + ((kc + 2) % NSTAGE) * STAGE, A, B,
                       m0, (kc + 2) * KC, M, tid);
            cp_commit();
        }
        const unsigned st = sbase + (kc % NSTAGE) * STAGE;
#pragma unroll
        for (int kk = 0; kk < 4; kk++) {
            const int k = kk * 16;
            int ar = lane & 15;
            int ac = k + ((lane >> 4) << 3);
            unsigned ah[2][4];
            ldsm4(ah[0][0], ah[0][1], ah[0][2], ah[0][3], st + aoff(wm + ar, ac));
            ldsm4(ah[1][0], ah[1][1], ah[1][2], ah[1][3], st + aoff(wm + 16 + ar, ac));
            int br = (lane & 7) + ((lane >> 4) << 3);
            int bc = k + (((lane >> 3) & 1) << 3);
            unsigned b[8][2];
#pragma unroll
            for (int q = 0; q < 4; q++)
                ldsm4(b[2*q][0], b[2*q][1], b[2*q+1][0], b[2*q+1][1],
                      st + 16384 + aoff(wn + 16 * q + br, bc));
#pragma unroll
            for (int mt = 0; mt < 2; mt++)
#pragma unroll
                for (int nt = 0; nt < 8; nt++)
                    mma16816(acc[mt][nt], ah[mt], b[nt]);
        }
    }

    // ---- store C ----
#pragma unroll
    for (int mt = 0; mt < 2; mt++) {
        int r0 = m0 + wm + mt * 16 + (lane >> 2);
#pragma unroll
        for (int nt = 0; nt < 8; nt++) {
            int c0 = nb + wn + nt * 8 + (lane & 3) * 2;
            if (r0 < M)
                *(__half2*)&C[(size_t)r0 * ldc + c0] =
                    __floats2half2_rn(acc[mt][nt][0], acc[mt][nt][1]);
            if (r0 + 8 < M)
                *(__half2*)&C[(size_t)(r0 + 8) * ldc + c0] =
                    __floats2half2_rn(acc[mt][nt][2], acc[mt][nt][3]);
        }
    }

    // ---- fused attention-scalar dots from fp32 accumulators ----
    if (MODE == 1) {
        // warp sub-tile = 32 nodes x one full head (64 cols). Exact dots.
        const int h = (nb + wn) >> 6;
        float a1v[16], a2v[16];
#pragma unroll
        for (int nt = 0; nt < 8; nt++)
#pragma unroll
            for (int q = 0; q < 2; q++) {
                int cc = nt * 8 + (lane & 3) * 2 + q;
                a1v[nt * 2 + q] = av1[h * 128 + cc];
                a2v[nt * 2 + q] = av1[h * 128 + 64 + cc];
            }
#pragma unroll
        for (int mt = 0; mt < 2; mt++) {
            float s1a = 0.f, s2a = 0.f, s1b = 0.f, s2b = 0.f;
#pragma unroll
            for (int nt = 0; nt < 8; nt++)
#pragma unroll
                for (int q = 0; q < 2; q++) {
                    float a1 = a1v[nt * 2 + q], a2 = a2v[nt * 2 + q];
                    s1a += acc[mt][nt][q]     * a1;
                    s2a += acc[mt][nt][q]     * a2;
                    s1b += acc[mt][nt][2 + q] * a1;
                    s2b += acc[mt][nt][2 + q] * a2;
                }
#pragma unroll
            for (int off = 1; off <= 2; off <<= 1) {
                s1a += __shfl_xor_sync(0xffffffffu, s1a, off);
                s2a += __shfl_xor_sync(0xffffffffu, s2a, off);
                s1b += __shfl_xor_sync(0xffffffffu, s1b, off);
                s2b += __shfl_xor_sync(0xffffffffu, s2b, off);
            }
            if ((lane & 3) == 0) {
                int r0 = m0 + wm + mt * 16 + (lane >> 2);
                if (r0 < M) {
                    g_s1[r0 * 8 + h] = s1a;
                    g_s2[r0 * 8 + h] = s2a;
                }
                if (r0 + 8 < M) {
                    g_s1[(r0 + 8) * 8 + h] = s1b;
                    g_s2[(r0 + 8) * 8 + h] = s2b;
                }
            }
        }
    } else if (MODE == 2) {
        // nb==0 -> mu (av1=mua), nb==128 -> lv (av2=lva). 128-col dot spans
        // 2 warps -> quad-reduce then atomicAdd (targets zeroed up front).
        const float* a = (nb == 0) ? av1 : av2;
        float* t1 = (nb == 0) ? g_smu1 : g_slv1;
        float* t2 = (nb == 0) ? g_smu2 : g_slv2;
        float a1v[16], a2v[16];
#pragma unroll
        for (int nt = 0; nt < 8; nt++)
#pragma unroll
            for (int q = 0; q < 2; q++) {
                int cc = wn + nt * 8 + (lane & 3) * 2 + q;
                a1v[nt * 2 + q] = a[cc];
                a2v[nt * 2 + q] = a[128 + cc];
            }
#pragma unroll
        for (int mt = 0; mt < 2; mt++) {
            float s1a = 0.f, s2a = 0.f, s1b = 0.f, s2b = 0.f;
#pragma unroll
            for (int nt = 0; nt < 8; nt++)
#pragma unroll
                for (int q = 0; q < 2; q++) {
                    float a1 = a1v[nt * 2 + q], a2 = a2v[nt * 2 + q];
                    s1a += acc[mt][nt][q]     * a1;
                    s2a += acc[mt][nt][q]     * a2;
                    s1b += acc[mt][nt][2 + q] * a1;
                    s2b += acc[mt][nt][2 + q] * a2;
                }
#pragma unroll
            for (int off = 1; off <= 2; off <<= 1) {
                s1a += __shfl_xor_sync(0xffffffffu, s1a, off);
                s2a += __shfl_xor_sync(0xffffffffu, s2a, off);
                s1b += __shfl_xor_sync(0xffffffffu, s1b, off);
                s2b += __shfl_xor_sync(0xffffffffu, s2b, off);
            }
            if ((lane & 3) == 0) {
                int r0 = m0 + wm + mt * 16 + (lane >> 2);
                if (r0 < M) {
                    atomicAdd(&t1[r0], s1a);
                    atomicAdd(&t2[r0], s2a);
                }
                if (r0 + 8 < M) {
                    atomicAdd(&t1[r0 + 8], s1b);
                    atomicAdd(&t2[r0 + 8], s2b);
                }
            }
        }
    }
}

// ---------------- layer-1 aggregation: warp-per-node, fp16 gather ----------
__global__ __launch_bounds__(256) void agg1_kernel(int N) {
    int n = (blockIdx.x * 256 + threadIdx.x) >> 5;
    if (n >= N) return;
    const int lane = threadIdx.x & 31;
    const int le = lane >> 3, hh = lane & 7;   // weight phase: edge-in-4, head
    const int hme = lane >> 2;                 // my head for gather/denominator
    const int beg = g_rowptr[n];
    const int deg = g_rowptr[n + 1] - beg;

    const float s1v = g_s1[n * 8 + hh];
    float acc[16];
#pragma unroll
    for (int i = 0; i < 16; i++) acc[i] = 0.f;
    float den = 0.f;

    for (int eb = 0; eb < deg; eb += 4) {
        const int cnt = min(4, deg - eb);
        int d_le = g_col[beg + ((le < cnt) ? (eb + le) : 0)];
        float logit = s1v + g_s2[d_le * 8 + hh];
        float lr = logit > 0.f ? logit : 0.2f * logit;
        float w_le = __expf(-lr);
#pragma unroll 4
        for (int e = 0; e < cnt; e++) {
            int   d = __shfl_sync(0xffffffffu, d_le, e << 3);
            float w = __shfl_sync(0xffffffffu, w_le, (e << 3) + hme);
            const uint4* hr = (const uint4*)(g_hh + (size_t)d * X2DIM) + lane * 2;
            uint4 pa = hr[0], pb = hr[1];
            const __half2* ha = (const __half2*)&pa;
            const __half2* hb = (const __half2*)&pb;
#pragma unroll
            for (int j = 0; j < 4; j++) {
                float2 fa = __half22float2(ha[j]);
                float2 fb = __half22float2(hb[j]);
                acc[2*j]     += w * fa.x; acc[2*j + 1] += w * fa.y;
                acc[8 + 2*j] += w * fb.x; acc[8 + 2*j + 1] += w * fb.y;
            }
            den += w;
        }
    }

    const float inv = 1.f / den;
    __half hi[16];
#pragma unroll
    for (int i = 0; i < 16; i++) {
        float t = acc[i] * inv;
        t = t > 0.f ? t : expm1f(t);
        hi[i] = __float2half_rn(t);
    }
    size_t o = (size_t)n * X2DIM + lane * 16;
    ((uint4*)(g_x2h + o))[0] = *(uint4*)(hi);
    ((uint4*)(g_x2h + o))[1] = *(uint4*)(hi + 8);
}

// ---------------- layer-2 aggregation: warp-per-node, fp16 gather ----------
__global__ __launch_bounds__(256) void agg2_kernel(
    const float* __restrict__ eps, float* __restrict__ out, int N)
{
    int n = (blockIdx.x * 256 + threadIdx.x) >> 5;
    if (n >= N) return;
    const int lane = threadIdx.x & 31;
    const int beg = g_rowptr[n];
    const int deg = g_rowptr[n + 1] - beg;
    const float bmu = g_smu1[n], blv = g_slv1[n];

    float amu[4] = {0,0,0,0}, alv[4] = {0,0,0,0};
    float dmu = 0.f, dlv = 0.f;

    for (int eb = 0; eb < deg; eb += 32) {
        const int cnt = min(32, deg - eb);
        int d_l = g_col[beg + ((lane < cnt) ? (eb + lane) : 0)];
        float lmu = bmu + g_smu2[d_l];
        float llv = blv + g_slv2[d_l];
        lmu = lmu > 0.f ? lmu : 0.2f * lmu;
        llv = llv > 0.f ? llv : 0.2f * llv;
        float wmu_l = __expf(-lmu);
        float wlv_l = __expf(-llv);
#pragma unroll 4
        for (int e = 0; e < cnt; e++) {
            int   d   = __shfl_sync(0xffffffffu, d_l,   e);
            float wmu = __shfl_sync(0xffffffffu, wmu_l, e);
            float wlv = __shfl_sync(0xffffffffu, wlv_l, e);
            const __half* base = g_hml + (size_t)d * 256;
            uint2 pm = *(const uint2*)(base + lane * 4);
            uint2 pl = *(const uint2*)(base + 128 + lane * 4);
            const __half2* hm = (const __half2*)&pm;
            const __half2* hl = (const __half2*)&pl;
            float2 m0 = __half22float2(hm[0]), m1 = __half22float2(hm[1]);
            float2 l0 = __half22float2(hl[0]), l1 = __half22float2(hl[1]);
            amu[0] += wmu * m0.x; amu[1] += wmu * m0.y;
            amu[2] += wmu * m1.x; amu[3] += wmu * m1.y;
            alv[0] += wlv * l0.x; alv[1] += wlv * l0.y;
            alv[2] += wlv * l1.x; alv[3] += wlv * l1.y;
            dmu += wmu; dlv += wlv;
        }
    }

    const float imu = 1.f / dmu, ilv = 1.f / dlv;
    float4 mu = make_float4(amu[0]*imu, amu[1]*imu, amu[2]*imu, amu[3]*imu);
    float4 lv = make_float4(alv[0]*ilv, alv[1]*ilv, alv[2]*ilv, alv[3]*ilv);
    float4 ev = *(const float4*)(eps + (size_t)n * NOUT + lane * 4);
    float4 z  = make_float4(ev.x * expf(lv.x) + mu.x,
                            ev.y * expf(lv.y) + mu.y,
                            ev.z * expf(lv.z) + mu.z,
                            ev.w * expf(lv.w) + mu.w);
    size_t NO = (size_t)N * NOUT;
    size_t o  = (size_t)n * NOUT + lane * 4;
    *(float4*)(out + o)          = z;
    *(float4*)(out + NO + o)     = mu;
    *(float4*)(out + 2 * NO + o) = lv;
}

// ---------------- host orchestration ----------------
extern "C" void kernel_launch(void* const* d_in, const int* in_sizes, int n_in,
                              void* d_out, int out_size)
{
    const float* x   = (const float*)d_in[0];
    const float* Ws  = (const float*)d_in[1];
    const float* As  = (const float*)d_in[2];
    const float* muW = (const float*)d_in[3];
    const float* mua = (const float*)d_in[4];
    const float* lvW = (const float*)d_in[5];
    const float* lva = (const float*)d_in[6];
    const float* eps = (const float*)d_in[7];
    const int*   ei  = (const int*)d_in[8];
    int E = in_sizes[8] / 2;
    int N = in_sizes[0] / NFEAT;
    float* out = (float*)d_out;

    __half *p_hh, *p_hml, *p_xh, *p_x2h, *p_bt1, *p_bt2;
    cudaGetSymbolAddress((void**)&p_hh,   g_hh);
    cudaGetSymbolAddress((void**)&p_hml,  g_hml);
    cudaGetSymbolAddress((void**)&p_xh,   g_xh);
    cudaGetSymbolAddress((void**)&p_x2h,  g_x2h);
    cudaGetSymbolAddress((void**)&p_bt1,  g_bt1);
    cudaGetSymbolAddress((void**)&p_bt2,  g_bt2);

    cudaFuncSetAttribute(gemm_tc<1>, cudaFuncAttributeMaxDynamicSharedMemorySize,
                         NSTAGE * STAGE);
    cudaFuncSetAttribute(gemm_tc<2>, cudaFuncAttributeMaxDynamicSharedMemorySize,
                         NSTAGE * STAGE);

    // side stream + events for graph-fork (created once; host-side resources)
    static cudaStream_t sB = nullptr;
    static cudaEvent_t eFork = nullptr, eJoin = nullptr;
    if (!sB) {
        cudaStreamCreateWithFlags(&sB, cudaStreamNonBlocking);
        cudaEventCreateWithFlags(&eFork, cudaEventDisableTiming);
        cudaEventCreateWithFlags(&eJoin, cudaEventDisableTiming);
    }

    int mtiles = (N + 127) / 128;
    int wblocks = (N + 7) / 8;     // warp-per-node kernels: 8 warps/block

    // fork: CSR chain (+ scalar-target zeroing) on side stream
    cudaEventRecord(eFork, 0);
    cudaStreamWaitEvent(sB, eFork, 0);

    convert_x_kernel<<<(N * NFEAT / 4 + 255) / 256, 256>>>(x, N * NFEAT / 4);       // 0
    convert_w_kernel<<<(512 * 512 + 256 * 512 + 255) / 256, 256>>>(Ws, muW, lvW);   // 1
    zero_kernel<<<(N + 255) / 256, 256, 0, sB>>>(N);                                 // 2
    gemm_tc<1><<<dim3(4, mtiles), 256, NSTAGE * STAGE>>>(p_xh, p_bt1, p_hh,          // 3
                                                         N, X2DIM, As, nullptr);
    hist_kernel<<<(E + 255) / 256, 256, 0, sB>>>(ei, E);                             // 4
    scan_kernel<<<1, 1024, 0, sB>>>(N);                                              // 5
    fill_kernel<<<(E + 255) / 256, 256, 0, sB>>>(ei, E);                             // 6
    cudaEventRecord(eJoin, sB);

    cudaStreamWaitEvent(0, eJoin, 0);   // join: agg1 needs CSR (+zeroed targets)
    agg1_kernel<<<wblocks, 256>>>(N);                                                // 7
    gemm_tc<2><<<dim3(2, mtiles), 256, NSTAGE * STAGE>>>(p_x2h, p_bt2, p_hml,        // 8
                                                         N, 256, mua, lva);
    agg2_kernel<<<wblocks, 256>>>(eps, out, N);                                      // 9
}